// round 6
// baseline (speedup 1.0000x reference)
#include <cuda_runtime.h>

#define NHN 50000
#define NGN 50000
#define NEDGE 1600000

// Scratch (static __device__ arrays: allocation-free per harness rules)
__device__ float g_P[NHN * 128];    // x_h @ W1a[:, :64]^T + b1a
__device__ float g_AGG[NGN * 128];  // scatter-sum of leaky(z_e)
__device__ float g_CNT[NGN];        // edge count per target node (float)
__device__ float g_A[NGN * 128];    // AGG @ W1b^T + cnt*b1b
__device__ float g_H[NGN * 128];    // hidden of node MLP

__global__ void zero_kernel() {
    int idx = blockIdx.x * blockDim.x + threadIdx.x;
    int stride = gridDim.x * blockDim.x;
    float4 z4 = make_float4(0.f, 0.f, 0.f, 0.f);
    float4* a4 = (float4*)g_AGG;
    for (int i = idx; i < NGN * 32; i += stride) a4[i] = z4;
    for (int i = idx; i < NGN; i += stride) g_CNT[i] = 0.f;
}

// ---------------------------------------------------------------------------
// Edge kernel: z = attr[e] @ W1a[:,64:]^T + P[src[e]] ; s = leaky(z) ;
// scatter s into g_AGG[tgt[e]] via float4 atomics (smem transpose first).
// 256 threads: j = tid&127 owns output col j (16 float4 weights in regs),
// half = tid>>7 picks 8 of the 16 staged edges.
// ---------------------------------------------------------------------------
__global__ __launch_bounds__(256) void edge_kernel(
    const float* __restrict__ attr, const int* __restrict__ eidx,
    const float* __restrict__ W1a)
{
    __shared__ __align__(16) float sbuf[128 * 65];  // W staging, then attr4+s_out
    __shared__ int src_s[16], tgt_s[16];
    int tid = threadIdx.x;
    int j = tid & 127;
    int half = tid >> 7;

    // Stage attr-half of W1a coalesced into padded smem, copy own row to regs
    for (int idx = tid; idx < 128 * 64; idx += 256) {
        int row = idx >> 6, k = idx & 63;
        sbuf[row * 65 + k] = W1a[row * 128 + 64 + k];
    }
    __syncthreads();
    float4 wreg[16];
#pragma unroll
    for (int k4 = 0; k4 < 16; k4++)
        wreg[k4] = make_float4(sbuf[j * 65 + 4 * k4 + 0], sbuf[j * 65 + 4 * k4 + 1],
                               sbuf[j * 65 + 4 * k4 + 2], sbuf[j * 65 + 4 * k4 + 3]);
    __syncthreads();

    float4* attr4 = (float4*)sbuf;        // [16 edges][16 float4]  (floats 0..1023)
    float* s_out = sbuf + 1024;           // [16 edges][128]        (floats 1024..3071)

    for (int base = blockIdx.x * 16; base < NEDGE; base += gridDim.x * 16) {
        if (tid < 16) {
            src_s[tid] = eidx[base + tid];
            tgt_s[tid] = eidx[NEDGE + base + tid];
        }
        const float4* gin = (const float4*)attr + (long long)base * 16;
        attr4[tid] = gin[tid];
        __syncthreads();

        const float4* as4 = attr4 + half * 8 * 16;
        float acc[8];
#pragma unroll
        for (int m = 0; m < 8; m++) acc[m] = 0.f;
#pragma unroll
        for (int k4 = 0; k4 < 16; k4++) {
            float4 w = wreg[k4];
#pragma unroll
            for (int m = 0; m < 8; m++) {
                float4 a = as4[m * 16 + k4];
                acc[m] += a.x * w.x + a.y * w.y + a.z * w.z + a.w * w.w;
            }
        }
#pragma unroll
        for (int m = 0; m < 8; m++) {
            int e = half * 8 + m;
            float z = acc[m] + __ldg(&g_P[(long long)src_s[e] * 128 + j]);
            s_out[e * 128 + j] = z >= 0.f ? z : 0.1f * z;
        }
        __syncthreads();

        // Scatter: 16 edges x 32 float4 = 512 vector atomics, 2 per thread
#pragma unroll
        for (int r = 0; r < 2; r++) {
            int tt = tid + r * 256;
            int e = tt >> 5, c4 = tt & 31;
            float4 v = ((const float4*)s_out)[e * 32 + c4];
            atomicAdd((float4*)&g_AGG[(long long)tgt_s[e] * 128 + c4 * 4], v);
        }
        if (tid < 16) atomicAdd(&g_CNT[tgt_s[tid]], 1.0f);
        __syncthreads();
    }
}

// ---------------------------------------------------------------------------
// Row GEMM: out[n][j] = in[n] . W[j,:K] + bias[j] (+ cnt[n]*cntb[j])
// in staged as float4 (LDS.128 broadcast); W transposed in smem.
// ---------------------------------------------------------------------------
template <int K, bool CNTB>
__global__ __launch_bounds__(256) void row_kernel(
    const float* __restrict__ in, const float* __restrict__ W, int ldw,
    const float* __restrict__ bias, const float* __restrict__ cntb,
    float* __restrict__ out, int N)
{
    extern __shared__ __align__(16) float sm[];
    constexpr int KC4 = K / 4;
    float* Ws = sm;                       // [K][128]
    float4* in4 = (float4*)(sm + K * 128);  // [16][KC4]
    int tid = threadIdx.x, j = tid & 127, half = tid >> 7;

    for (int idx = tid; idx < K * 128; idx += 256) {
        int kk = idx >> 7, jj = idx & 127;
        Ws[idx] = W[jj * ldw + kk];
    }
    __syncthreads();
    float bj = bias ? bias[j] : 0.f;
    float cbj = CNTB ? cntb[j] : 0.f;

    for (int base = blockIdx.x * 16; base < N; base += gridDim.x * 16) {
        const float4* gin = (const float4*)in + (long long)base * KC4;
        for (int idx = tid; idx < 16 * KC4; idx += 256) in4[idx] = gin[idx];
        __syncthreads();

        const float4* is4 = in4 + half * 8 * KC4;
        float acc[8];
#pragma unroll
        for (int m = 0; m < 8; m++) acc[m] = 0.f;
#pragma unroll 8
        for (int k4 = 0; k4 < KC4; k4++) {
            float w0 = Ws[(4 * k4 + 0) * 128 + j];
            float w1 = Ws[(4 * k4 + 1) * 128 + j];
            float w2 = Ws[(4 * k4 + 2) * 128 + j];
            float w3 = Ws[(4 * k4 + 3) * 128 + j];
#pragma unroll
            for (int m = 0; m < 8; m++) {
                float4 a = is4[m * KC4 + k4];
                acc[m] += a.x * w0 + a.y * w1 + a.z * w2 + a.w * w3;
            }
        }
#pragma unroll
        for (int m = 0; m < 8; m++) {
            int n = base + half * 8 + m;
            float v = acc[m] + bj;
            if (CNTB) v += g_CNT[n] * cbj;
            out[(long long)n * 128 + j] = v;
        }
        __syncthreads();
    }
}

// ---------------------------------------------------------------------------
// Node MLP hidden: H = leaky( [x_g | A | u[batch]] @ W2a^T + b2a ), K = 320
// ---------------------------------------------------------------------------
__global__ __launch_bounds__(256) void nodeH_kernel(
    const float* __restrict__ xg, const float* __restrict__ u,
    const int* __restrict__ batch, const float* __restrict__ W2a,
    const float* __restrict__ b2a, int N)
{
    extern __shared__ __align__(16) float sm[];
    float* Ws = sm;                 // [320][128]
    float* in_s = sm + 320 * 128;   // [16][320]
    int tid = threadIdx.x, j = tid & 127, half = tid >> 7;

    for (int idx = tid; idx < 320 * 128; idx += 256) {
        int kk = idx >> 7, jj = idx & 127;
        Ws[idx] = W2a[jj * 320 + kk];
    }
    __syncthreads();
    float bj = b2a[j];

    for (int base = blockIdx.x * 16; base < N; base += gridDim.x * 16) {
        for (int idx = tid; idx < 16 * 128; idx += 256) {
            int m = idx >> 7, c = idx & 127;
            in_s[m * 320 + c] = xg[(long long)base * 128 + idx];
            in_s[m * 320 + 128 + c] = g_A[(long long)base * 128 + idx];
        }
        for (int idx = tid; idx < 16 * 64; idx += 256) {
            int m = idx >> 6, c = idx & 63;
            in_s[m * 320 + 256 + c] = u[batch[base + m] * 64 + c];
        }
        __syncthreads();

        const float4* is4 = (const float4*)(in_s) + half * 8 * 80;
        float acc[8];
#pragma unroll
        for (int m = 0; m < 8; m++) acc[m] = 0.f;
#pragma unroll 8
        for (int k4 = 0; k4 < 80; k4++) {
            float w0 = Ws[(4 * k4 + 0) * 128 + j];
            float w1 = Ws[(4 * k4 + 1) * 128 + j];
            float w2 = Ws[(4 * k4 + 2) * 128 + j];
            float w3 = Ws[(4 * k4 + 3) * 128 + j];
#pragma unroll
            for (int m = 0; m < 8; m++) {
                float4 a = is4[m * 80 + k4];
                acc[m] += a.x * w0 + a.y * w1 + a.z * w2 + a.w * w3;
            }
        }
#pragma unroll
        for (int m = 0; m < 8; m++) {
            int n = base + half * 8 + m;
            float v = acc[m] + bj;
            v = v >= 0.f ? v : 0.1f * v;
            g_H[(long long)n * 128 + j] = v;
        }
        __syncthreads();
    }
}

extern "C" void kernel_launch(void* const* d_in, const int* in_sizes, int n_in,
                              void* d_out, int out_size)
{
    const float* x_h = (const float*)d_in[0];
    const float* x_g = (const float*)d_in[1];
    const float* eattr = (const float*)d_in[2];
    const float* u = (const float*)d_in[3];
    const float* W1a = (const float*)d_in[4];
    const float* b1a = (const float*)d_in[5];
    const float* W1b = (const float*)d_in[6];
    const float* b1b = (const float*)d_in[7];
    const float* W2a = (const float*)d_in[8];
    const float* b2a = (const float*)d_in[9];
    const float* W2b = (const float*)d_in[10];
    const float* b2b = (const float*)d_in[11];
    const int* eidx = (const int*)d_in[12];    // int32
    const int* batch = (const int*)d_in[13];   // int32
    float* out = (float*)d_out;

    float *pP, *pAGG, *pA, *pH;
    cudaGetSymbolAddress((void**)&pP, g_P);
    cudaGetSymbolAddress((void**)&pAGG, g_AGG);
    cudaGetSymbolAddress((void**)&pA, g_A);
    cudaGetSymbolAddress((void**)&pH, g_H);

    size_t smem64 = (size_t)(64 * 128) * 4 + (size_t)(16 * 16) * 16;
    size_t smem128 = (size_t)(128 * 128) * 4 + (size_t)(16 * 32) * 16;
    size_t smem320 = (size_t)(320 * 128 + 16 * 320) * 4;
    cudaFuncSetAttribute(row_kernel<64, false>,
                         cudaFuncAttributeMaxDynamicSharedMemorySize, (int)smem64);
    cudaFuncSetAttribute(row_kernel<128, true>,
                         cudaFuncAttributeMaxDynamicSharedMemorySize, (int)smem128);
    cudaFuncSetAttribute(row_kernel<128, false>,
                         cudaFuncAttributeMaxDynamicSharedMemorySize, (int)smem128);
    cudaFuncSetAttribute(nodeH_kernel,
                         cudaFuncAttributeMaxDynamicSharedMemorySize, (int)smem320);

    // 1. clear accumulators
    zero_kernel<<<512, 256>>>();
    // 2. P = x_h @ W1a[:, :64]^T + b1a   (folds edge bias per-source-node)
    row_kernel<64, false><<<625, 256, smem64>>>(x_h, W1a, 128, b1a,
                                                nullptr, pP, NHN);
    // 3. per-edge attr GEMM + leaky + float4 atomic scatter
    edge_kernel<<<592, 256>>>(eattr, eidx, W1a);
    // 4. A = AGG @ W1b^T + cnt * b1b
    row_kernel<128, true><<<500, 256, smem128>>>(pAGG, W1b, 128, nullptr,
                                                 b1b, pA, NGN);
    // 5. H = leaky([x_g | A | u[batch]] @ W2a^T + b2a)
    nodeH_kernel<<<296, 256, smem320>>>(x_g, u, batch, W2a, b2a, NGN);
    // 6. out = H @ W2b^T + b2b
    row_kernel<128, false><<<500, 256, smem128>>>(pH, W2b, 128, b2b,
                                                  nullptr, out, NGN);
}

// round 7
// speedup vs baseline: 1.0482x; 1.0482x over previous
#include <cuda_runtime.h>

#define NHN 50000
#define NGN 50000
#define NEDGE 1600000

// Scratch (static __device__ arrays: allocation-free per harness rules)
__device__ float g_P[NHN * 128];    // x_h @ W1a[:, :64]^T + b1a
__device__ float g_AGG[NGN * 128];  // scatter-sum of leaky(z_e)
__device__ float g_CNT[NGN];        // edge count per target node
__device__ float g_A[NGN * 128];    // AGG @ W1b^T + cnt*b1b
__device__ float g_H[NGN * 128];    // hidden of node MLP

__global__ void zero4_kernel(float4* p, int n4) {
    int idx = blockIdx.x * blockDim.x + threadIdx.x;
    float4 z = make_float4(0.f, 0.f, 0.f, 0.f);
    for (int i = idx; i < n4; i += gridDim.x * blockDim.x) p[i] = z;
}
__global__ void zero_last_kernel(float4* p, int n4) {
    int idx = blockIdx.x * blockDim.x + threadIdx.x;
    float4 z = make_float4(0.f, 0.f, 0.f, 0.f);
    for (int i = idx; i < n4; i += gridDim.x * blockDim.x) p[i] = z;
    for (int i = idx; i < NGN; i += gridDim.x * blockDim.x) g_CNT[i] = 0.f;
}

// FMA micro-tile: acc[4][4] += a[e].{x,y,z,w} * w{0..3}.{col}
#define FMA_TILE(acc, a0, a1, a2, a3, w0, w1, w2, w3)                          \
    {                                                                          \
        float4 _a[4] = {a0, a1, a2, a3};                                       \
        _Pragma("unroll") for (int _e = 0; _e < 4; _e++) {                     \
            acc[_e][0] += _a[_e].x * w0.x + _a[_e].y * w1.x +                  \
                          _a[_e].z * w2.x + _a[_e].w * w3.x;                   \
            acc[_e][1] += _a[_e].x * w0.y + _a[_e].y * w1.y +                  \
                          _a[_e].z * w2.y + _a[_e].w * w3.y;                   \
            acc[_e][2] += _a[_e].x * w0.z + _a[_e].y * w1.z +                  \
                          _a[_e].z * w2.z + _a[_e].w * w3.z;                   \
            acc[_e][3] += _a[_e].x * w0.w + _a[_e].y * w1.w +                  \
                          _a[_e].z * w2.w + _a[_e].w * w3.w;                   \
        }                                                                      \
    }

// ---------------------------------------------------------------------------
// Edge kernel: tile = 32 edges x 128 cols; thread (j=tid&31, m=tid>>5) owns
// edges 4m..4m+3, cols 4j..4j+3. z = attr @ W1a_x^T + P[src]; leaky; float4
// atomic scatter of own 4x4 block into g_AGG[tgt].
// ---------------------------------------------------------------------------
__global__ __launch_bounds__(256) void edge_kernel(
    const float* __restrict__ attr, const int* __restrict__ eidx,
    const float* __restrict__ W1a)
{
    __shared__ __align__(16) float Wt[64 * 128];    // Wt[k][c] = W1a[c][64+k]
    __shared__ __align__(16) float attr_s[32 * 64];
    __shared__ int src_s[32], tgt_s[32];
    int tid = threadIdx.x;
    int j = tid & 31, m = tid >> 5;

    for (int idx = tid; idx < 64 * 128; idx += 256) {
        int k = idx & 63, c = idx >> 6;          // k fast: coalesced LDG
        Wt[k * 128 + c] = W1a[c * 128 + 64 + k]; // one-time STS conflicts: ok
    }
    __syncthreads();

    const float4* Wt4 = (const float4*)Wt;
    const float4* as4 = (const float4*)attr_s;

    for (int t = blockIdx.x; t < NEDGE / 32; t += gridDim.x) {
        int base = t * 32;
        if (tid < 32) {
            src_s[tid] = eidx[base + tid];
            tgt_s[tid] = eidx[NEDGE + base + tid];
        }
        const float4* ga = (const float4*)attr + (long long)base * 16;
        ((float4*)attr_s)[tid] = ga[tid];
        ((float4*)attr_s)[tid + 256] = ga[tid + 256];
        __syncthreads();

        float acc[4][4] = {};
#pragma unroll
        for (int k4 = 0; k4 < 16; k4++) {
            float4 a0 = as4[(4 * m + 0) * 16 + k4];
            float4 a1 = as4[(4 * m + 1) * 16 + k4];
            float4 a2 = as4[(4 * m + 2) * 16 + k4];
            float4 a3 = as4[(4 * m + 3) * 16 + k4];
            float4 w0 = Wt4[(4 * k4 + 0) * 32 + j];
            float4 w1 = Wt4[(4 * k4 + 1) * 32 + j];
            float4 w2 = Wt4[(4 * k4 + 2) * 32 + j];
            float4 w3 = Wt4[(4 * k4 + 3) * 32 + j];
            FMA_TILE(acc, a0, a1, a2, a3, w0, w1, w2, w3)
        }

#pragma unroll
        for (int e = 0; e < 4; e++) {
            int edge = 4 * m + e;
            int s = src_s[edge], tg = tgt_s[edge];
            float4 p = *(const float4*)&g_P[(long long)s * 128 + 4 * j];
            float4 v;
            v.x = acc[e][0] + p.x; v.x = v.x >= 0.f ? v.x : 0.1f * v.x;
            v.y = acc[e][1] + p.y; v.y = v.y >= 0.f ? v.y : 0.1f * v.y;
            v.z = acc[e][2] + p.z; v.z = v.z >= 0.f ? v.z : 0.1f * v.z;
            v.w = acc[e][3] + p.w; v.w = v.w >= 0.f ? v.w : 0.1f * v.w;
            atomicAdd((float4*)&g_AGG[(long long)tg * 128 + 4 * j], v);
        }
        if (tid < 32) atomicAdd(&g_CNT[tgt_s[tid]], 1.f);
        __syncthreads();
    }
}

// ---------------------------------------------------------------------------
// Row GEMM: out[n][c] = in[n,:K] . W[c,:K] + bias (MODE 0) or + cnt[n]*b (MODE 1)
// tile 32 rows x 128 cols, thread 4x4 block. W rows have stride 128.
// ---------------------------------------------------------------------------
template <int K, int MODE>
__global__ __launch_bounds__(256) void row_kernel(
    const float* __restrict__ in, const float* __restrict__ W,
    const float* __restrict__ bvec, float* __restrict__ out, int N)
{
    extern __shared__ __align__(16) float sm[];
    constexpr int K4 = K / 4;
    float* Wt = sm;               // [K][128]
    float* in_s = sm + K * 128;   // [32][K]
    int tid = threadIdx.x;
    int j = tid & 31, m = tid >> 5;

    for (int idx = tid; idx < K * 128; idx += 256) {
        int k = idx % K, c = idx / K;
        Wt[k * 128 + c] = W[c * 128 + k];
    }
    __syncthreads();

    float4 b4 = *(const float4*)&bvec[4 * j];
    const float4* Wt4 = (const float4*)Wt;
    const float4* is4 = (const float4*)in_s;
    int nt = (N + 31) >> 5;

    for (int t = blockIdx.x; t < nt; t += gridDim.x) {
        int base = t * 32;
        for (int idx = tid; idx < 32 * K4; idx += 256) {
            int r = idx / K4, kq = idx % K4;
            int rg = base + r; if (rg > N - 1) rg = N - 1;
            ((float4*)in_s)[idx] = ((const float4*)in)[(long long)rg * K4 + kq];
        }
        __syncthreads();

        float acc[4][4] = {};
#pragma unroll 8
        for (int k4 = 0; k4 < K4; k4++) {
            float4 a0 = is4[(4 * m + 0) * K4 + k4];
            float4 a1 = is4[(4 * m + 1) * K4 + k4];
            float4 a2 = is4[(4 * m + 2) * K4 + k4];
            float4 a3 = is4[(4 * m + 3) * K4 + k4];
            float4 w0 = Wt4[(4 * k4 + 0) * 32 + j];
            float4 w1 = Wt4[(4 * k4 + 1) * 32 + j];
            float4 w2 = Wt4[(4 * k4 + 2) * 32 + j];
            float4 w3 = Wt4[(4 * k4 + 3) * 32 + j];
            FMA_TILE(acc, a0, a1, a2, a3, w0, w1, w2, w3)
        }

#pragma unroll
        for (int e = 0; e < 4; e++) {
            int r = base + 4 * m + e;
            if (r < N) {
                float sc = (MODE == 1) ? g_CNT[r] : 1.f;
                float4 v;
                v.x = acc[e][0] + sc * b4.x;
                v.y = acc[e][1] + sc * b4.y;
                v.z = acc[e][2] + sc * b4.z;
                v.w = acc[e][3] + sc * b4.w;
                *(float4*)&out[(long long)r * 128 + 4 * j] = v;
            }
        }
        __syncthreads();
    }
}

// ---------------------------------------------------------------------------
// Node MLP hidden: H = leaky([x_g | A | u[batch]] @ W2a^T + b2a), K = 320.
// Full W2a^T resident in smem (160KB) staged once; in rows concat-staged.
// ---------------------------------------------------------------------------
__global__ __launch_bounds__(256) void nodeH_kernel(
    const float* __restrict__ xg, const float* __restrict__ u,
    const int* __restrict__ batch, const float* __restrict__ W2a,
    const float* __restrict__ b2a, int N)
{
    extern __shared__ __align__(16) float sm[];
    float* Wt = sm;                 // [320][128]
    float* in_s = sm + 320 * 128;   // [32][320]
    int tid = threadIdx.x;
    int j = tid & 31, m = tid >> 5;

    for (int idx = tid; idx < 320 * 128; idx += 256) {
        int k = idx % 320, c = idx / 320;
        Wt[k * 128 + c] = W2a[c * 320 + k];
    }
    __syncthreads();

    float4 b4 = *(const float4*)&b2a[4 * j];
    const float4* Wt4 = (const float4*)Wt;
    const float4* is4 = (const float4*)in_s;
    int nt = (N + 31) >> 5;

    for (int t = blockIdx.x; t < nt; t += gridDim.x) {
        int base = t * 32;
        for (int idx = tid; idx < 32 * 80; idx += 256) {
            int r = idx / 80, q = idx % 80;
            int rg = base + r; if (rg > N - 1) rg = N - 1;
            float4 v;
            if (q < 32)       v = ((const float4*)xg)[(long long)rg * 32 + q];
            else if (q < 64)  v = ((const float4*)g_A)[(long long)rg * 32 + (q - 32)];
            else              v = ((const float4*)u)[batch[rg] * 16 + (q - 64)];
            ((float4*)in_s)[idx] = v;
        }
        __syncthreads();

        float acc[4][4] = {};
#pragma unroll 8
        for (int k4 = 0; k4 < 80; k4++) {
            float4 a0 = is4[(4 * m + 0) * 80 + k4];
            float4 a1 = is4[(4 * m + 1) * 80 + k4];
            float4 a2 = is4[(4 * m + 2) * 80 + k4];
            float4 a3 = is4[(4 * m + 3) * 80 + k4];
            float4 w0 = Wt4[(4 * k4 + 0) * 32 + j];
            float4 w1 = Wt4[(4 * k4 + 1) * 32 + j];
            float4 w2 = Wt4[(4 * k4 + 2) * 32 + j];
            float4 w3 = Wt4[(4 * k4 + 3) * 32 + j];
            FMA_TILE(acc, a0, a1, a2, a3, w0, w1, w2, w3)
        }

#pragma unroll
        for (int e = 0; e < 4; e++) {
            int r = base + 4 * m + e;
            if (r < N) {
                float4 v;
                v.x = acc[e][0] + b4.x; v.x = v.x >= 0.f ? v.x : 0.1f * v.x;
                v.y = acc[e][1] + b4.y; v.y = v.y >= 0.f ? v.y : 0.1f * v.y;
                v.z = acc[e][2] + b4.z; v.z = v.z >= 0.f ? v.z : 0.1f * v.z;
                v.w = acc[e][3] + b4.w; v.w = v.w >= 0.f ? v.w : 0.1f * v.w;
                *(float4*)&g_H[(long long)r * 128 + 4 * j] = v;
            }
        }
        __syncthreads();
    }
}

extern "C" void kernel_launch(void* const* d_in, const int* in_sizes, int n_in,
                              void* d_out, int out_size)
{
    const float* x_h = (const float*)d_in[0];
    const float* x_g = (const float*)d_in[1];
    const float* eattr = (const float*)d_in[2];
    const float* u = (const float*)d_in[3];
    const float* W1a = (const float*)d_in[4];
    const float* b1a = (const float*)d_in[5];
    const float* W1b = (const float*)d_in[6];
    const float* b1b = (const float*)d_in[7];
    const float* W2a = (const float*)d_in[8];
    const float* b2a = (const float*)d_in[9];
    const float* W2b = (const float*)d_in[10];
    const float* b2b = (const float*)d_in[11];
    const int* eidx = (const int*)d_in[12];   // int32
    const int* batch = (const int*)d_in[13];  // int32
    float* out = (float*)d_out;

    float *pP, *pAGG, *pA;
    cudaGetSymbolAddress((void**)&pP, g_P);
    cudaGetSymbolAddress((void**)&pAGG, g_AGG);
    cudaGetSymbolAddress((void**)&pA, g_A);
    float* pH;
    cudaGetSymbolAddress((void**)&pH, g_H);

    size_t smem64 = (size_t)(64 * 128 + 32 * 64) * 4;     // 40960
    size_t smem128 = (size_t)(128 * 128 + 32 * 128) * 4;  // 81920
    size_t smem320 = (size_t)(320 * 128 + 32 * 320) * 4;  // 204800
    cudaFuncSetAttribute(row_kernel<64, 0>,
                         cudaFuncAttributeMaxDynamicSharedMemorySize, (int)smem64);
    cudaFuncSetAttribute(row_kernel<128, 1>,
                         cudaFuncAttributeMaxDynamicSharedMemorySize, (int)smem128);
    cudaFuncSetAttribute(row_kernel<128, 0>,
                         cudaFuncAttributeMaxDynamicSharedMemorySize, (int)smem128);
    cudaFuncSetAttribute(nodeH_kernel,
                         cudaFuncAttributeMaxDynamicSharedMemorySize, (int)smem320);

    int q4 = NGN * 32 / 4;  // quarter of AGG in float4s
    // 1-4: clear accumulators (split so edge_kernel is launch #6)
    zero4_kernel<<<264, 256>>>((float4*)pAGG, q4);
    zero4_kernel<<<264, 256>>>((float4*)pAGG + q4, q4);
    zero4_kernel<<<264, 256>>>((float4*)pAGG + 2 * q4, q4);
    zero_last_kernel<<<264, 256>>>((float4*)pAGG + 3 * q4, q4);
    // 5: P = x_h @ W1a[:, :64]^T + b1a
    row_kernel<64, 0><<<1563, 256, smem64>>>(x_h, W1a, b1a, pP, NHN);
    // 6: per-edge attr GEMM + leaky + float4 atomic scatter
    edge_kernel<<<1184, 256>>>(eattr, eidx, W1a);
    // 7: A = AGG @ W1b^T + cnt * b1b
    row_kernel<128, 1><<<1563, 256, smem128>>>(pAGG, W1b, b1b, pA, NGN);
    // 8: H = leaky([x_g | A | u[batch]] @ W2a^T + b2a)
    nodeH_kernel<<<1563, 256, smem320>>>(x_g, u, batch, W2a, b2a, NGN);
    // 9: out = H @ W2b^T + b2b
    row_kernel<128, 0><<<1563, 256, smem128>>>(pH, W2b, b2b, out, NGN);
}

// round 8
// speedup vs baseline: 1.2157x; 1.1598x over previous
#include <cuda_runtime.h>

#define NHN 50000
#define NGN 50000
#define NEDGE 1600000

// Scratch (static __device__ arrays: allocation-free per harness rules)
__device__ float g_P[NHN * 128];    // x_h @ W1a[:, :64]^T + b1a
__device__ float g_AGG[NGN * 128];  // per-target sum of leaky(z_e)
__device__ float g_CNT[NGN];        // edge count per target node
__device__ float g_A[NGN * 128];    // AGG @ W1b^T + cnt*b1b
__device__ float g_H[NGN * 128];    // hidden of node MLP
__device__ int g_hist[NGN];
__device__ int g_off[NGN + 1];
__device__ int g_cursor[NGN];
__device__ int g_seid[NEDGE];       // edge ids sorted by target
__device__ int g_ssrc[NEDGE];       // src ids sorted by target

__global__ void zero_hist_kernel() {
    int idx = blockIdx.x * blockDim.x + threadIdx.x;
    for (int i = idx; i < NGN; i += gridDim.x * blockDim.x) g_hist[i] = 0;
}

__global__ void hist_kernel(const int* __restrict__ eidx) {
    int idx = blockIdx.x * blockDim.x + threadIdx.x;
    for (int e = idx; e < NEDGE; e += gridDim.x * blockDim.x)
        atomicAdd(&g_hist[eidx[NEDGE + e]], 1);
}

// Single-CTA exclusive scan over 50K bins; also emits cursor copy + float CNT.
__global__ __launch_bounds__(1024) void scan_kernel() {
    __shared__ int s[1024];
    __shared__ int carry_s;
    int tid = threadIdx.x;
    if (tid == 0) carry_s = 0;
    __syncthreads();
    for (int base = 0; base < NGN; base += 1024) {
        int i = base + tid;
        int orig = (i < NGN) ? g_hist[i] : 0;
        s[tid] = orig;
        __syncthreads();
        for (int d = 1; d < 1024; d <<= 1) {
            int t2 = (tid >= d) ? s[tid - d] : 0;
            __syncthreads();
            s[tid] += t2;
            __syncthreads();
        }
        int incl = s[tid];
        int carry = carry_s;
        if (i < NGN) {
            int excl = carry + incl - orig;
            g_off[i] = excl;
            g_cursor[i] = excl;
            g_CNT[i] = (float)orig;
        }
        __syncthreads();
        if (tid == 1023) carry_s = carry + incl;
        __syncthreads();
    }
    if (tid == 0) g_off[NGN] = carry_s;
}

__global__ void permute_kernel(const int* __restrict__ eidx) {
    int idx = blockIdx.x * blockDim.x + threadIdx.x;
    for (int e = idx; e < NEDGE; e += gridDim.x * blockDim.x) {
        int t = eidx[NEDGE + e];
        int pos = atomicAdd(&g_cursor[t], 1);
        g_seid[pos] = e;
        g_ssrc[pos] = eidx[e];
    }
}

// FMA micro-tile: acc[4][4] += a[e].{x,y,z,w} * w{0..3}.{col}
#define FMA_TILE(acc, a0, a1, a2, a3, w0, w1, w2, w3)                          \
    {                                                                          \
        float4 _a[4] = {a0, a1, a2, a3};                                       \
        _Pragma("unroll") for (int _e = 0; _e < 4; _e++) {                     \
            acc[_e][0] += _a[_e].x * w0.x + _a[_e].y * w1.x +                  \
                          _a[_e].z * w2.x + _a[_e].w * w3.x;                   \
            acc[_e][1] += _a[_e].x * w0.y + _a[_e].y * w1.y +                  \
                          _a[_e].z * w2.y + _a[_e].w * w3.y;                   \
            acc[_e][2] += _a[_e].x * w0.z + _a[_e].y * w1.z +                  \
                          _a[_e].z * w2.z + _a[_e].w * w3.z;                   \
            acc[_e][3] += _a[_e].x * w0.w + _a[_e].y * w1.w +                  \
                          _a[_e].z * w2.w + _a[_e].w * w3.w;                   \
        }                                                                      \
    }

// ---------------------------------------------------------------------------
// CSR gather aggregation: CTA loops over targets t; per target, chunks of 32
// sorted edges; z = attr[eid] @ W1a_x^T + P[src]; leaky; register-accumulate;
// cross-warp smem reduce; single STG per target. NO global atomics.
// ---------------------------------------------------------------------------
__global__ __launch_bounds__(256) void agg_kernel(
    const float* __restrict__ attr, const float* __restrict__ W1a)
{
    __shared__ __align__(16) float Wt[64 * 128];   // Wt[k][c] = W1a[c][64+k]
    __shared__ __align__(16) float attr_s[32 * 64];
    __shared__ __align__(16) float red[8 * 128];
    __shared__ int es[32], ss[32];
    int tid = threadIdx.x;
    int j = tid & 31, m = tid >> 5;

    for (int idx = tid; idx < 64 * 128; idx += 256) {
        int k = idx & 63, c = idx >> 6;
        Wt[k * 128 + c] = W1a[c * 128 + 64 + k];
    }
    __syncthreads();

    const float4* Wt4 = (const float4*)Wt;
    const float4* as4 = (const float4*)attr_s;
    const float4* attr4 = (const float4*)attr;
    const float4* P4 = (const float4*)g_P;

    for (int t = blockIdx.x; t < NGN; t += gridDim.x) {
        int beg = g_off[t], end = g_off[t + 1];
        float sum0 = 0.f, sum1 = 0.f, sum2 = 0.f, sum3 = 0.f;

        for (int cb = beg; cb < end; cb += 32) {
            int n = end - cb; if (n > 32) n = 32;
            if (tid < 32) {
                if (tid < n) { es[tid] = g_seid[cb + tid]; ss[tid] = g_ssrc[cb + tid]; }
                else ss[tid] = -1;
            }
            __syncthreads();
            for (int i = tid; i < 512; i += 256) {
                int r = i >> 4, q = i & 15;
                ((float4*)attr_s)[i] = (r < n)
                    ? attr4[(long long)es[r] * 16 + q]
                    : make_float4(0.f, 0.f, 0.f, 0.f);
            }
            __syncthreads();

            float acc[4][4] = {};
#pragma unroll
            for (int k4 = 0; k4 < 16; k4++) {
                float4 a0 = as4[(4 * m + 0) * 16 + k4];
                float4 a1 = as4[(4 * m + 1) * 16 + k4];
                float4 a2 = as4[(4 * m + 2) * 16 + k4];
                float4 a3 = as4[(4 * m + 3) * 16 + k4];
                float4 w0 = Wt4[(4 * k4 + 0) * 32 + j];
                float4 w1 = Wt4[(4 * k4 + 1) * 32 + j];
                float4 w2 = Wt4[(4 * k4 + 2) * 32 + j];
                float4 w3 = Wt4[(4 * k4 + 3) * 32 + j];
                FMA_TILE(acc, a0, a1, a2, a3, w0, w1, w2, w3)
            }
#pragma unroll
            for (int e = 0; e < 4; e++) {
                int s = ss[4 * m + e];
                if (s >= 0) {
                    float4 p = P4[(long long)s * 32 + j];
                    float z;
                    z = acc[e][0] + p.x; sum0 += z >= 0.f ? z : 0.1f * z;
                    z = acc[e][1] + p.y; sum1 += z >= 0.f ? z : 0.1f * z;
                    z = acc[e][2] + p.z; sum2 += z >= 0.f ? z : 0.1f * z;
                    z = acc[e][3] + p.w; sum3 += z >= 0.f ? z : 0.1f * z;
                }
            }
            __syncthreads();
        }

        *(float4*)&red[m * 128 + 4 * j] = make_float4(sum0, sum1, sum2, sum3);
        __syncthreads();
        if (tid < 128) {
            float s = 0.f;
#pragma unroll
            for (int mm = 0; mm < 8; mm++) s += red[mm * 128 + tid];
            g_AGG[(long long)t * 128 + tid] = s;
        }
        __syncthreads();
    }
}

// ---------------------------------------------------------------------------
// Row GEMM: out[n][c] = in[n,:K] . W[c,:K] + bias (MODE 0) or + cnt[n]*b (MODE 1)
// ---------------------------------------------------------------------------
template <int K, int MODE>
__global__ __launch_bounds__(256) void row_kernel(
    const float* __restrict__ in, const float* __restrict__ W,
    const float* __restrict__ bvec, float* __restrict__ out, int N)
{
    extern __shared__ __align__(16) float sm[];
    constexpr int K4 = K / 4;
    float* Wt = sm;               // [K][128]
    float* in_s = sm + K * 128;   // [32][K]
    int tid = threadIdx.x;
    int j = tid & 31, m = tid >> 5;

    for (int idx = tid; idx < K * 128; idx += 256) {
        int k = idx % K, c = idx / K;
        Wt[k * 128 + c] = W[c * 128 + k];
    }
    __syncthreads();

    float4 b4 = *(const float4*)&bvec[4 * j];
    const float4* Wt4 = (const float4*)Wt;
    const float4* is4 = (const float4*)in_s;
    int nt = (N + 31) >> 5;

    for (int t = blockIdx.x; t < nt; t += gridDim.x) {
        int base = t * 32;
        for (int idx = tid; idx < 32 * K4; idx += 256) {
            int r = idx / K4, kq = idx % K4;
            int rg = base + r; if (rg > N - 1) rg = N - 1;
            ((float4*)in_s)[idx] = ((const float4*)in)[(long long)rg * K4 + kq];
        }
        __syncthreads();

        float acc[4][4] = {};
#pragma unroll 8
        for (int k4 = 0; k4 < K4; k4++) {
            float4 a0 = is4[(4 * m + 0) * K4 + k4];
            float4 a1 = is4[(4 * m + 1) * K4 + k4];
            float4 a2 = is4[(4 * m + 2) * K4 + k4];
            float4 a3 = is4[(4 * m + 3) * K4 + k4];
            float4 w0 = Wt4[(4 * k4 + 0) * 32 + j];
            float4 w1 = Wt4[(4 * k4 + 1) * 32 + j];
            float4 w2 = Wt4[(4 * k4 + 2) * 32 + j];
            float4 w3 = Wt4[(4 * k4 + 3) * 32 + j];
            FMA_TILE(acc, a0, a1, a2, a3, w0, w1, w2, w3)
        }
#pragma unroll
        for (int e = 0; e < 4; e++) {
            int r = base + 4 * m + e;
            if (r < N) {
                float sc = (MODE == 1) ? g_CNT[r] : 1.f;
                float4 v;
                v.x = acc[e][0] + sc * b4.x;
                v.y = acc[e][1] + sc * b4.y;
                v.z = acc[e][2] + sc * b4.z;
                v.w = acc[e][3] + sc * b4.w;
                *(float4*)&out[(long long)r * 128 + 4 * j] = v;
            }
        }
        __syncthreads();
    }
}

// ---------------------------------------------------------------------------
// Node MLP hidden: H = leaky([x_g | A | u[batch]] @ W2a^T + b2a), K = 320.
// ---------------------------------------------------------------------------
__global__ __launch_bounds__(256) void nodeH_kernel(
    const float* __restrict__ xg, const float* __restrict__ u,
    const int* __restrict__ batch, const float* __restrict__ W2a,
    const float* __restrict__ b2a, int N)
{
    extern __shared__ __align__(16) float sm[];
    float* Wt = sm;                 // [320][128]
    float* in_s = sm + 320 * 128;   // [32][320]
    int tid = threadIdx.x;
    int j = tid & 31, m = tid >> 5;

    for (int idx = tid; idx < 320 * 128; idx += 256) {
        int k = idx % 320, c = idx / 320;
        Wt[k * 128 + c] = W2a[c * 320 + k];
    }
    __syncthreads();

    float4 b4 = *(const float4*)&b2a[4 * j];
    const float4* Wt4 = (const float4*)Wt;
    const float4* is4 = (const float4*)in_s;
    int nt = (N + 31) >> 5;

    for (int t = blockIdx.x; t < nt; t += gridDim.x) {
        int base = t * 32;
        for (int idx = tid; idx < 32 * 80; idx += 256) {
            int r = idx / 80, q = idx % 80;
            int rg = base + r; if (rg > N - 1) rg = N - 1;
            float4 v;
            if (q < 32)       v = ((const float4*)xg)[(long long)rg * 32 + q];
            else if (q < 64)  v = ((const float4*)g_A)[(long long)rg * 32 + (q - 32)];
            else              v = ((const float4*)u)[batch[rg] * 16 + (q - 64)];
            ((float4*)in_s)[idx] = v;
        }
        __syncthreads();

        float acc[4][4] = {};
#pragma unroll 8
        for (int k4 = 0; k4 < 80; k4++) {
            float4 a0 = is4[(4 * m + 0) * 80 + k4];
            float4 a1 = is4[(4 * m + 1) * 80 + k4];
            float4 a2 = is4[(4 * m + 2) * 80 + k4];
            float4 a3 = is4[(4 * m + 3) * 80 + k4];
            float4 w0 = Wt4[(4 * k4 + 0) * 32 + j];
            float4 w1 = Wt4[(4 * k4 + 1) * 32 + j];
            float4 w2 = Wt4[(4 * k4 + 2) * 32 + j];
            float4 w3 = Wt4[(4 * k4 + 3) * 32 + j];
            FMA_TILE(acc, a0, a1, a2, a3, w0, w1, w2, w3)
        }
#pragma unroll
        for (int e = 0; e < 4; e++) {
            int r = base + 4 * m + e;
            if (r < N) {
                float4 v;
                v.x = acc[e][0] + b4.x; v.x = v.x >= 0.f ? v.x : 0.1f * v.x;
                v.y = acc[e][1] + b4.y; v.y = v.y >= 0.f ? v.y : 0.1f * v.y;
                v.z = acc[e][2] + b4.z; v.z = v.z >= 0.f ? v.z : 0.1f * v.z;
                v.w = acc[e][3] + b4.w; v.w = v.w >= 0.f ? v.w : 0.1f * v.w;
                *(float4*)&g_H[(long long)r * 128 + 4 * j] = v;
            }
        }
        __syncthreads();
    }
}

extern "C" void kernel_launch(void* const* d_in, const int* in_sizes, int n_in,
                              void* d_out, int out_size)
{
    const float* x_h = (const float*)d_in[0];
    const float* x_g = (const float*)d_in[1];
    const float* eattr = (const float*)d_in[2];
    const float* u = (const float*)d_in[3];
    const float* W1a = (const float*)d_in[4];
    const float* b1a = (const float*)d_in[5];
    const float* W1b = (const float*)d_in[6];
    const float* b1b = (const float*)d_in[7];
    const float* W2a = (const float*)d_in[8];
    const float* b2a = (const float*)d_in[9];
    const float* W2b = (const float*)d_in[10];
    const float* b2b = (const float*)d_in[11];
    const int* eidx = (const int*)d_in[12];   // int32
    const int* batch = (const int*)d_in[13];  // int32
    float* out = (float*)d_out;

    float *pP, *pAGG, *pA, *pH;
    cudaGetSymbolAddress((void**)&pP, g_P);
    cudaGetSymbolAddress((void**)&pAGG, g_AGG);
    cudaGetSymbolAddress((void**)&pA, g_A);
    cudaGetSymbolAddress((void**)&pH, g_H);

    size_t smem64 = (size_t)(64 * 128 + 32 * 64) * 4;
    size_t smem128 = (size_t)(128 * 128 + 32 * 128) * 4;
    size_t smem320 = (size_t)(320 * 128 + 32 * 320) * 4;
    cudaFuncSetAttribute(row_kernel<64, 0>,
                         cudaFuncAttributeMaxDynamicSharedMemorySize, (int)smem64);
    cudaFuncSetAttribute(row_kernel<128, 1>,
                         cudaFuncAttributeMaxDynamicSharedMemorySize, (int)smem128);
    cudaFuncSetAttribute(row_kernel<128, 0>,
                         cudaFuncAttributeMaxDynamicSharedMemorySize, (int)smem128);
    cudaFuncSetAttribute(nodeH_kernel,
                         cudaFuncAttributeMaxDynamicSharedMemorySize, (int)smem320);

    // 1-4: counting sort of edges by target (CSR)
    zero_hist_kernel<<<196, 256>>>();
    hist_kernel<<<1184, 256>>>(eidx);
    scan_kernel<<<1, 1024>>>();
    permute_kernel<<<1184, 256>>>(eidx);
    // 5: P = x_h @ W1a[:, :64]^T + b1a
    row_kernel<64, 0><<<1563, 256, smem64>>>(x_h, W1a, b1a, pP, NHN);
    // 6: gather-aggregate (atomic-free)
    agg_kernel<<<1480, 256>>>(eattr, W1a);
    // 7: A = AGG @ W1b^T + cnt * b1b
    row_kernel<128, 1><<<1563, 256, smem128>>>(pAGG, W1b, b1b, pA, NGN);
    // 8: H = leaky([x_g | A | u[batch]] @ W2a^T + b2a)
    nodeH_kernel<<<1563, 256, smem320>>>(x_g, u, batch, W2a, b2a, NGN);
    // 9: out = H @ W2b^T + b2b
    row_kernel<128, 0><<<1563, 256, smem128>>>(pH, W2b, b2b, out, NGN);
}

// round 10
// speedup vs baseline: 1.3438x; 1.1053x over previous
#include <cuda_runtime.h>
#include <cuda_bf16.h>
#include <cstdint>

#define NHN 50000
#define NGN 50000
#define NEDGE 1600000
#define NTILE (NEDGE / 128)

// Scratch (static __device__ arrays: allocation-free per harness rules)
__device__ float g_P[NHN * 128];    // x_h @ W1a[:, :64]^T + b1a
__device__ float g_AGG[NGN * 128];  // per-target sum of leaky(z_e)
__device__ float g_CNT[NGN];        // edge count per target node
__device__ float g_A[NGN * 128];    // AGG @ W1b^T + cnt*b1b
__device__ float g_H[NGN * 128];    // hidden of node MLP
__device__ int g_hist[NGN];
__device__ int g_off[NGN + 1];
__device__ int g_cursor[NGN];
__device__ int g_seid[NEDGE];  // edge ids sorted by target
__device__ int g_ssrc[NEDGE];  // src ids sorted by target
__device__ int g_stgt[NEDGE];  // tgt ids sorted (nondecreasing)

__global__ void zero_all_kernel() {
    int idx = blockIdx.x * blockDim.x + threadIdx.x;
    int stride = gridDim.x * blockDim.x;
    float4 z = make_float4(0.f, 0.f, 0.f, 0.f);
    float4* a4 = (float4*)g_AGG;
    for (int i = idx; i < NGN * 32; i += stride) a4[i] = z;
    for (int i = idx; i < NGN; i += stride) g_hist[i] = 0;
}

__global__ void hist_kernel(const int* __restrict__ eidx) {
    int idx = blockIdx.x * blockDim.x + threadIdx.x;
    for (int e = idx; e < NEDGE; e += gridDim.x * blockDim.x)
        atomicAdd(&g_hist[eidx[NEDGE + e]], 1);
}

// Single-CTA exclusive scan over 50K bins; also emits cursor copy + float CNT.
__global__ __launch_bounds__(1024) void scan_kernel() {
    __shared__ int s_scan[1024];
    __shared__ int carry_s;
    int tid = threadIdx.x;
    if (tid == 0) carry_s = 0;
    __syncthreads();
    for (int base = 0; base < NGN; base += 1024) {
        int i = base + tid;
        int orig = (i < NGN) ? g_hist[i] : 0;
        s_scan[tid] = orig;
        __syncthreads();
        for (int d = 1; d < 1024; d <<= 1) {
            int t2 = (tid >= d) ? s_scan[tid - d] : 0;
            __syncthreads();
            s_scan[tid] += t2;
            __syncthreads();
        }
        int incl = s_scan[tid];
        int carry = carry_s;
        if (i < NGN) {
            int excl = carry + incl - orig;
            g_off[i] = excl;
            g_cursor[i] = excl;
            g_CNT[i] = (float)orig;
        }
        __syncthreads();
        if (tid == 1023) carry_s = carry + incl;
        __syncthreads();
    }
    if (tid == 0) g_off[NGN] = carry_s;
}

__global__ void permute_kernel(const int* __restrict__ eidx) {
    int idx = blockIdx.x * blockDim.x + threadIdx.x;
    for (int e = idx; e < NEDGE; e += gridDim.x * blockDim.x) {
        int t = eidx[NEDGE + e];
        int pos = atomicAdd(&g_cursor[t], 1);
        g_seid[pos] = e;
        g_ssrc[pos] = eidx[e];
        g_stgt[pos] = t;
    }
}

// ---------------- mma / ldmatrix helpers ----------------
__device__ __forceinline__ void ldmx4(unsigned& r0, unsigned& r1, unsigned& r2,
                                      unsigned& r3, const void* p) {
    unsigned a = (unsigned)__cvta_generic_to_shared(p);
    asm volatile("ldmatrix.sync.aligned.m8n8.x4.shared.b16 {%0,%1,%2,%3}, [%4];"
                 : "=r"(r0), "=r"(r1), "=r"(r2), "=r"(r3) : "r"(a));
}
__device__ __forceinline__ void ldmx2(unsigned& r0, unsigned& r1, const void* p) {
    unsigned a = (unsigned)__cvta_generic_to_shared(p);
    asm volatile("ldmatrix.sync.aligned.m8n8.x2.shared.b16 {%0,%1}, [%2];"
                 : "=r"(r0), "=r"(r1) : "r"(a));
}
__device__ __forceinline__ void mma_bf16(float* d, unsigned a0, unsigned a1,
                                         unsigned a2, unsigned a3,
                                         unsigned b0, unsigned b1) {
    asm volatile(
        "mma.sync.aligned.m16n8k16.row.col.f32.bf16.bf16.f32 "
        "{%0,%1,%2,%3}, {%4,%5,%6,%7}, {%8,%9}, {%0,%1,%2,%3};"
        : "+f"(d[0]), "+f"(d[1]), "+f"(d[2]), "+f"(d[3])
        : "r"(a0), "r"(a1), "r"(a2), "r"(a3), "r"(b0), "r"(b1));
}
__device__ __forceinline__ void split2(float x, float y, unsigned& hi, unsigned& lo) {
    __nv_bfloat16 hx = __float2bfloat16_rn(x), hy = __float2bfloat16_rn(y);
    __nv_bfloat16 lx = __float2bfloat16_rn(x - __bfloat162float(hx));
    __nv_bfloat16 ly = __float2bfloat16_rn(y - __bfloat162float(hy));
    __nv_bfloat162 h2, l2;
    h2.x = hx; h2.y = hy; l2.x = lx; l2.y = ly;
    hi = *(unsigned*)&h2;
    lo = *(unsigned*)&l2;
}

// ---------------------------------------------------------------------------
// Tensor-core aggregation over flat tiles of 128 sorted edges.
// Z = attr_tile @ W1a_x^T via 3-pass split-bf16 mma (fp32-class precision);
// epilogue: + P[src] (fp32), leaky, per-warp segmented reduce over sorted
// targets, one float4 atomicAdd per segment.
// SMEM: Whi/Wlo [128][72]bf16; union{ Ahi/Alo [128][72]bf16 | S[8][16][68]f32 };
// es/ss/ts [128]int.  Total 75264 B -> 2 CTAs/SM.
// ---------------------------------------------------------------------------
__global__ __launch_bounds__(256) void agg_kernel(
    const float* __restrict__ attr, const float* __restrict__ W1a)
{
    extern __shared__ __align__(16) char smag[];
    __nv_bfloat16* Whi = (__nv_bfloat16*)smag;
    __nv_bfloat16* Wlo = (__nv_bfloat16*)(smag + 18432);
    __nv_bfloat16* Ahi = (__nv_bfloat16*)(smag + 36864);
    __nv_bfloat16* Alo = (__nv_bfloat16*)(smag + 36864 + 18432);
    int* es = (int*)(smag + 73728);
    int* ss = (int*)(smag + 74240);
    int* ts = (int*)(smag + 74752);

    int tid = threadIdx.x;
    int lane = tid & 31, w = tid >> 5;

    // Stage W1a[:,64:] as split bf16, layout [n=128][k=64], row stride 72
    for (int idx = tid; idx < 128 * 64; idx += 256) {
        int c = idx >> 6, k = idx & 63;
        float x = W1a[c * 128 + 64 + k];
        __nv_bfloat16 h = __float2bfloat16_rn(x);
        Whi[c * 72 + k] = h;
        Wlo[c * 72 + k] = __float2bfloat16_rn(x - __bfloat162float(h));
    }

    int a_row = ((lane >> 3) & 1) * 8 + (lane & 7);
    int a_kof = ((lane >> 4) & 1) * 8;
    int b_n = lane & 7;
    int b_kof = ((lane >> 3) & 1) * 8;
    int rowb = w * 16;
    int r0 = lane >> 2, c2 = 2 * (lane & 3);
    const float4* attr4 = (const float4*)attr;
    float* S = (float*)(smag + 36864 + w * 4352);  // [16][68] per warp

    for (int t = blockIdx.x; t < NTILE; t += gridDim.x) {
        int base = t * 128;
        __syncthreads();  // S region (over A) free before restage
        if (tid < 128) {
            es[tid] = g_seid[base + tid];
            ss[tid] = g_ssrc[base + tid];
            ts[tid] = g_stgt[base + tid];
        }
        __syncthreads();
        // Gather 128 attr rows, split to bf16 hi/lo
        for (int i = tid; i < 2048; i += 256) {
            int r = i >> 4, q = i & 15;
            float4 v = attr4[(long long)es[r] * 16 + q];
            unsigned h01, l01, h23, l23;
            split2(v.x, v.y, h01, l01);
            split2(v.z, v.w, h23, l23);
            unsigned* dh = (unsigned*)(Ahi + r * 72 + 4 * q);
            unsigned* dl = (unsigned*)(Alo + r * 72 + 4 * q);
            dh[0] = h01; dh[1] = h23;
            dl[0] = l01; dl[1] = l23;
        }
        __syncthreads();

        float acc[16][4];
#pragma unroll
        for (int n = 0; n < 16; n++) {
            acc[n][0] = 0.f; acc[n][1] = 0.f; acc[n][2] = 0.f; acc[n][3] = 0.f;
        }

#pragma unroll
        for (int ks = 0; ks < 4; ks++) {
            unsigned ah0, ah1, ah2, ah3, al0, al1, al2, al3;
            const __nv_bfloat16* pa = Ahi + (rowb + a_row) * 72 + ks * 16 + a_kof;
            ldmx4(ah0, ah1, ah2, ah3, pa);
            const __nv_bfloat16* pl = Alo + (rowb + a_row) * 72 + ks * 16 + a_kof;
            ldmx4(al0, al1, al2, al3, pl);
#pragma unroll
            for (int nf = 0; nf < 16; nf++) {
                unsigned bh0, bh1, bl0, bl1;
                const __nv_bfloat16* pb = Whi + (8 * nf + b_n) * 72 + ks * 16 + b_kof;
                ldmx2(bh0, bh1, pb);
                const __nv_bfloat16* pbl = Wlo + (8 * nf + b_n) * 72 + ks * 16 + b_kof;
                ldmx2(bl0, bl1, pbl);
                mma_bf16(acc[nf], ah0, ah1, ah2, ah3, bh0, bh1);
                mma_bf16(acc[nf], ah0, ah1, ah2, ah3, bl0, bl1);
                mma_bf16(acc[nf], al0, al1, al2, al3, bh0, bh1);
            }
        }
        __syncthreads();  // A staging dead; S may overwrite

        int s0 = ss[rowb + r0], s1 = ss[rowb + r0 + 8];
#pragma unroll
        for (int h = 0; h < 2; h++) {
#pragma unroll
            for (int nq = 0; nq < 8; nq++) {
                int nf = 8 * h + nq;
                int gc = 8 * nf + c2;
                int lc = gc - 64 * h;
                float2 p0 = *(const float2*)&g_P[(long long)s0 * 128 + gc];
                float2 p1 = *(const float2*)&g_P[(long long)s1 * 128 + gc];
                float z0 = acc[nf][0] + p0.x; z0 = z0 >= 0.f ? z0 : 0.1f * z0;
                float z1 = acc[nf][1] + p0.y; z1 = z1 >= 0.f ? z1 : 0.1f * z1;
                float z2 = acc[nf][2] + p1.x; z2 = z2 >= 0.f ? z2 : 0.1f * z2;
                float z3 = acc[nf][3] + p1.y; z3 = z3 >= 0.f ? z3 : 0.1f * z3;
                *(float2*)&S[r0 * 68 + lc] = make_float2(z0, z1);
                *(float2*)&S[(r0 + 8) * 68 + lc] = make_float2(z2, z3);
            }
            __syncwarp();
            if (lane < 16) {
                int i = 0;
                while (i < 16) {
                    int tg = ts[rowb + i];
                    float4 s4 = make_float4(0.f, 0.f, 0.f, 0.f);
                    int jr = i;
                    do {
                        float4 v = *(const float4*)&S[jr * 68 + 4 * lane];
                        s4.x += v.x; s4.y += v.y; s4.z += v.z; s4.w += v.w;
                        jr++;
                    } while (jr < 16 && ts[rowb + jr] == tg);
                    atomicAdd((float4*)&g_AGG[(long long)tg * 128 + 64 * h + 4 * lane], s4);
                    i = jr;
                }
            }
            __syncwarp();
        }
    }
}

// FMA micro-tile: acc[4][4] += a[e].{x,y,z,w} * w{0..3}.{col}
#define FMA_TILE(acc, a0, a1, a2, a3, w0, w1, w2, w3)                          \
    {                                                                          \
        float4 _a[4] = {a0, a1, a2, a3};                                       \
        _Pragma("unroll") for (int _e = 0; _e < 4; _e++) {                     \
            acc[_e][0] += _a[_e].x * w0.x + _a[_e].y * w1.x +                  \
                          _a[_e].z * w2.x + _a[_e].w * w3.x;                   \
            acc[_e][1] += _a[_e].x * w0.y + _a[_e].y * w1.y +                  \
                          _a[_e].z * w2.y + _a[_e].w * w3.y;                   \
            acc[_e][2] += _a[_e].x * w0.z + _a[_e].y * w1.z +                  \
                          _a[_e].z * w2.z + _a[_e].w * w3.z;                   \
            acc[_e][3] += _a[_e].x * w0.w + _a[_e].y * w1.w +                  \
                          _a[_e].z * w2.w + _a[_e].w * w3.w;                   \
        }                                                                      \
    }

// ---------------------------------------------------------------------------
// Row GEMM: out[n][c] = in[n,:K] . W[c,:K] + bias (MODE 0) or + cnt[n]*b (MODE 1)
// ---------------------------------------------------------------------------
template <int K, int MODE>
__global__ __launch_bounds__(256) void row_kernel(
    const float* __restrict__ in, const float* __restrict__ W,
    const float* __restrict__ bvec, float* __restrict__ out, int N)
{
    extern __shared__ __align__(16) float smrow[];
    constexpr int K4 = K / 4;
    float* Wt = smrow;               // [K][128]
    float* in_s = smrow + K * 128;   // [32][K]
    int tid = threadIdx.x;
    int j = tid & 31, m = tid >> 5;

    for (int idx = tid; idx < K * 128; idx += 256) {
        int k = idx % K, c = idx / K;
        Wt[k * 128 + c] = W[c * 128 + k];
    }
    __syncthreads();

    float4 b4 = *(const float4*)&bvec[4 * j];
    const float4* Wt4 = (const float4*)Wt;
    const float4* is4 = (const float4*)in_s;
    int nt = (N + 31) >> 5;

    for (int t = blockIdx.x; t < nt; t += gridDim.x) {
        int base = t * 32;
        for (int idx = tid; idx < 32 * K4; idx += 256) {
            int r = idx / K4, kq = idx % K4;
            int rg = base + r; if (rg > N - 1) rg = N - 1;
            ((float4*)in_s)[idx] = ((const float4*)in)[(long long)rg * K4 + kq];
        }
        __syncthreads();

        float acc[4][4] = {};
#pragma unroll 8
        for (int k4 = 0; k4 < K4; k4++) {
            float4 a0 = is4[(4 * m + 0) * K4 + k4];
            float4 a1 = is4[(4 * m + 1) * K4 + k4];
            float4 a2 = is4[(4 * m + 2) * K4 + k4];
            float4 a3 = is4[(4 * m + 3) * K4 + k4];
            float4 w0 = Wt4[(4 * k4 + 0) * 32 + j];
            float4 w1 = Wt4[(4 * k4 + 1) * 32 + j];
            float4 w2 = Wt4[(4 * k4 + 2) * 32 + j];
            float4 w3 = Wt4[(4 * k4 + 3) * 32 + j];
            FMA_TILE(acc, a0, a1, a2, a3, w0, w1, w2, w3)
        }
#pragma unroll
        for (int e = 0; e < 4; e++) {
            int r = base + 4 * m + e;
            if (r < N) {
                float sc = (MODE == 1) ? g_CNT[r] : 1.f;
                float4 v;
                v.x = acc[e][0] + sc * b4.x;
                v.y = acc[e][1] + sc * b4.y;
                v.z = acc[e][2] + sc * b4.z;
                v.w = acc[e][3] + sc * b4.w;
                *(float4*)&out[(long long)r * 128 + 4 * j] = v;
            }
        }
        __syncthreads();
    }
}

// ---------------------------------------------------------------------------
// Node MLP hidden: H = leaky([x_g | A | u[batch]] @ W2a^T + b2a), K = 320.
// ---------------------------------------------------------------------------
__global__ __launch_bounds__(256) void nodeH_kernel(
    const float* __restrict__ xg, const float* __restrict__ u,
    const int* __restrict__ batch, const float* __restrict__ W2a,
    const float* __restrict__ b2a, int N)
{
    extern __shared__ __align__(16) float smnh[];
    float* Wt = smnh;                 // [320][128]
    float* in_s = smnh + 320 * 128;   // [32][320]
    int tid = threadIdx.x;
    int j = tid & 31, m = tid >> 5;

    for (int idx = tid; idx < 320 * 128; idx += 256) {
        int k = idx % 320, c = idx / 320;
        Wt[k * 128 + c] = W2a[c * 320 + k];
    }
    __syncthreads();

    float4 b4 = *(const float4*)&b2a[4 * j];
    const float4* Wt4 = (const float4*)Wt;
    const float4* is4 = (const float4*)in_s;
    int nt = (N + 31) >> 5;

    for (int t = blockIdx.x; t < nt; t += gridDim.x) {
        int base = t * 32;
        for (int idx = tid; idx < 32 * 80; idx += 256) {
            int r = idx / 80, q = idx % 80;
            int rg = base + r; if (rg > N - 1) rg = N - 1;
            float4 v;
            if (q < 32)      v = ((const float4*)xg)[(long long)rg * 32 + q];
            else if (q < 64) v = ((const float4*)g_A)[(long long)rg * 32 + (q - 32)];
            else             v = ((const float4*)u)[batch[rg] * 16 + (q - 64)];
            ((float4*)in_s)[idx] = v;
        }
        __syncthreads();

        float acc[4][4] = {};
#pragma unroll 8
        for (int k4 = 0; k4 < 80; k4++) {
            float4 a0 = is4[(4 * m + 0) * 80 + k4];
            float4 a1 = is4[(4 * m + 1) * 80 + k4];
            float4 a2 = is4[(4 * m + 2) * 80 + k4];
            float4 a3 = is4[(4 * m + 3) * 80 + k4];
            float4 w0 = Wt4[(4 * k4 + 0) * 32 + j];
            float4 w1 = Wt4[(4 * k4 + 1) * 32 + j];
            float4 w2 = Wt4[(4 * k4 + 2) * 32 + j];
            float4 w3 = Wt4[(4 * k4 + 3) * 32 + j];
            FMA_TILE(acc, a0, a1, a2, a3, w0, w1, w2, w3)
        }
#pragma unroll
        for (int e = 0; e < 4; e++) {
            int r = base + 4 * m + e;
            if (r < N) {
                float4 v;
                v.x = acc[e][0] + b4.x; v.x = v.x >= 0.f ? v.x : 0.1f * v.x;
                v.y = acc[e][1] + b4.y; v.y = v.y >= 0.f ? v.y : 0.1f * v.y;
                v.z = acc[e][2] + b4.z; v.z = v.z >= 0.f ? v.z : 0.1f * v.z;
                v.w = acc[e][3] + b4.w; v.w = v.w >= 0.f ? v.w : 0.1f * v.w;
                *(float4*)&g_H[(long long)r * 128 + 4 * j] = v;
            }
        }
        __syncthreads();
    }
}

extern "C" void kernel_launch(void* const* d_in, const int* in_sizes, int n_in,
                              void* d_out, int out_size)
{
    const float* x_h = (const float*)d_in[0];
    const float* x_g = (const float*)d_in[1];
    const float* eattr = (const float*)d_in[2];
    const float* u = (const float*)d_in[3];
    const float* W1a = (const float*)d_in[4];
    const float* b1a = (const float*)d_in[5];
    const float* W1b = (const float*)d_in[6];
    const float* b1b = (const float*)d_in[7];
    const float* W2a = (const float*)d_in[8];
    const float* b2a = (const float*)d_in[9];
    const float* W2b = (const float*)d_in[10];
    const float* b2b = (const float*)d_in[11];
    const int* eidx = (const int*)d_in[12];   // int32
    const int* batch = (const int*)d_in[13];  // int32
    float* out = (float*)d_out;

    float *pP, *pAGG, *pA, *pH;
    cudaGetSymbolAddress((void**)&pP, g_P);
    cudaGetSymbolAddress((void**)&pAGG, g_AGG);
    cudaGetSymbolAddress((void**)&pA, g_A);
    cudaGetSymbolAddress((void**)&pH, g_H);

    size_t smem64 = (size_t)(64 * 128 + 32 * 64) * 4;
    size_t smem128 = (size_t)(128 * 128 + 32 * 128) * 4;
    size_t smem320 = (size_t)(320 * 128 + 32 * 320) * 4;
    size_t smem_agg = 75264;
    cudaFuncSetAttribute(row_kernel<64, 0>,
                         cudaFuncAttributeMaxDynamicSharedMemorySize, (int)smem64);
    cudaFuncSetAttribute(row_kernel<128, 1>,
                         cudaFuncAttributeMaxDynamicSharedMemorySize, (int)smem128);
    cudaFuncSetAttribute(row_kernel<128, 0>,
                         cudaFuncAttributeMaxDynamicSharedMemorySize, (int)smem128);
    cudaFuncSetAttribute(nodeH_kernel,
                         cudaFuncAttributeMaxDynamicSharedMemorySize, (int)smem320);
    cudaFuncSetAttribute(agg_kernel,
                         cudaFuncAttributeMaxDynamicSharedMemorySize, (int)smem_agg);

    // 1: zero AGG + hist
    zero_all_kernel<<<592, 256>>>();
    // 2-4: counting sort of edges by target (CSR)
    hist_kernel<<<1184, 256>>>(eidx);
    scan_kernel<<<1, 1024>>>();
    permute_kernel<<<1184, 256>>>(eidx);
    // 5: P = x_h @ W1a[:, :64]^T + b1a
    row_kernel<64, 0><<<1563, 256, smem64>>>(x_h, W1a, b1a, pP, NHN);
    // 6: tensor-core aggregation over sorted edge tiles  (profiled launch)
    agg_kernel<<<296, 256, smem_agg>>>(eattr, W1a);
    // 7: A = AGG @ W1b^T + cnt * b1b
    row_kernel<128, 1><<<1563, 256, smem128>>>(pAGG, W1b, b1b, pA, NGN);
    // 8: H = leaky([x_g | A | u[batch]] @ W2a^T + b2a)
    nodeH_kernel<<<1563, 256, smem320>>>(x_g, u, batch, W2a, b2a, NGN);
    // 9: out = H @ W2b^T + b2b
    row_kernel<128, 0><<<1563, 256, smem128>>>(pH, W2b, b2b, out, NGN);
}

// round 12
// speedup vs baseline: 1.3675x; 1.0177x over previous
#include <cuda_runtime.h>
#include <cuda_bf16.h>
#include <cstdint>

#define NHN 50000
#define NGN 50000
#define NEDGE 1600000
#define NTILE (NEDGE / 128)

// Scratch (static __device__ arrays: allocation-free per harness rules).
// Zero-state protocol: g_hist and g_AGG start zero (static init) and every
// consumer restores them to zero after reading, so each graph replay sees
// identical starting state.
__device__ float g_P[NHN * 128];    // x_h @ W1a[:, :64]^T + b1a
__device__ float g_AGG[NGN * 128];  // per-target sum of leaky(z_e)
__device__ float g_CNT[NGN];        // edge count per target node
__device__ float g_A[NGN * 128];    // AGG @ W1b^T + cnt*b1b
__device__ float g_H[NGN * 128];    // hidden of node MLP
__device__ int g_hist[NGN];
__device__ int g_off[NGN + 1];
__device__ int g_cursor[NGN];
__device__ int g_seid[NEDGE];  // edge ids sorted by target
__device__ int g_ssrc[NEDGE];  // src ids sorted by target
__device__ int g_stgt[NEDGE];  // tgt ids sorted (nondecreasing)

// Warp-shuffle block scan over 50K bins, 3 barriers per 1024-block.
// Reads g_hist and restores it to zero; emits off, cursor, float CNT.
__global__ __launch_bounds__(1024) void scan_kernel() {
    __shared__ int wsum[32];
    __shared__ int carry_s;
    int tid = threadIdx.x;
    int lane = tid & 31, wid = tid >> 5;
    if (tid == 0) carry_s = 0;
    __syncthreads();
    for (int base = 0; base < NGN; base += 1024) {
        int i = base + tid;
        int orig = (i < NGN) ? g_hist[i] : 0;
        if (i < NGN) g_hist[i] = 0;  // restore for next replay
        int v = orig;
#pragma unroll
        for (int d = 1; d < 32; d <<= 1) {
            int t = __shfl_up_sync(0xFFFFFFFFu, v, d);
            if (lane >= d) v += t;
        }
        if (lane == 31) wsum[wid] = v;
        __syncthreads();
        if (wid == 0) {
            int s = wsum[lane];
#pragma unroll
            for (int d = 1; d < 32; d <<= 1) {
                int t = __shfl_up_sync(0xFFFFFFFFu, s, d);
                if (lane >= d) s += t;
            }
            wsum[lane] = s;
        }
        __syncthreads();
        int carry = carry_s;
        int incl = v + (wid ? wsum[wid - 1] : 0);
        if (i < NGN) {
            int excl = carry + incl - orig;
            g_off[i] = excl;
            g_cursor[i] = excl;
            g_CNT[i] = (float)orig;
        }
        __syncthreads();
        if (tid == 0) carry_s = carry + wsum[31];
        __syncthreads();
    }
    if (tid == 0) g_off[NGN] = carry_s;
}

__global__ void permute_kernel(const int* __restrict__ eidx) {
    int idx = blockIdx.x * blockDim.x + threadIdx.x;
    for (int e = idx; e < NEDGE; e += gridDim.x * blockDim.x) {
        int t = eidx[NEDGE + e];
        int pos = atomicAdd(&g_cursor[t], 1);
        g_seid[pos] = e;
        g_ssrc[pos] = eidx[e];
        g_stgt[pos] = t;
    }
}

// ---------------- mma / ldmatrix helpers ----------------
__device__ __forceinline__ void ldmx4(unsigned& r0, unsigned& r1, unsigned& r2,
                                      unsigned& r3, const void* p) {
    unsigned a = (unsigned)__cvta_generic_to_shared(p);
    asm volatile("ldmatrix.sync.aligned.m8n8.x4.shared.b16 {%0,%1,%2,%3}, [%4];"
                 : "=r"(r0), "=r"(r1), "=r"(r2), "=r"(r3) : "r"(a));
}
__device__ __forceinline__ void ldmx2(unsigned& r0, unsigned& r1, const void* p) {
    unsigned a = (unsigned)__cvta_generic_to_shared(p);
    asm volatile("ldmatrix.sync.aligned.m8n8.x2.shared.b16 {%0,%1}, [%2];"
                 : "=r"(r0), "=r"(r1) : "r"(a));
}
__device__ __forceinline__ void mma_bf16(float* d, unsigned a0, unsigned a1,
                                         unsigned a2, unsigned a3,
                                         unsigned b0, unsigned b1) {
    asm volatile(
        "mma.sync.aligned.m16n8k16.row.col.f32.bf16.bf16.f32 "
        "{%0,%1,%2,%3}, {%4,%5,%6,%7}, {%8,%9}, {%0,%1,%2,%3};"
        : "+f"(d[0]), "+f"(d[1]), "+f"(d[2]), "+f"(d[3])
        : "r"(a0), "r"(a1), "r"(a2), "r"(a3), "r"(b0), "r"(b1));
}
__device__ __forceinline__ void split2(float x, float y, unsigned& hi, unsigned& lo) {
    __nv_bfloat16 hx = __float2bfloat16_rn(x), hy = __float2bfloat16_rn(y);
    __nv_bfloat16 lx = __float2bfloat16_rn(x - __bfloat162float(hx));
    __nv_bfloat16 ly = __float2bfloat16_rn(y - __bfloat162float(hy));
    __nv_bfloat162 h2, l2;
    h2.x = hx; h2.y = hy; l2.x = lx; l2.y = ly;
    hi = *(unsigned*)&h2;
    lo = *(unsigned*)&l2;
}

// ---------------------------------------------------------------------------
// Tensor-core aggregation over flat tiles of 128 sorted edges (mma.sync —
// tcgen05 is unavailable: harness PTX targets compute_103, no 'a' features).
// Z = attr_tile @ W1a_x^T via 3-pass split-bf16 mma; epilogue: + P[src] fp32,
// leaky, per-warp segmented reduce over sorted targets, float4 atomics.
// ---------------------------------------------------------------------------
__global__ __launch_bounds__(256) void agg_kernel(
    const float* __restrict__ attr, const float* __restrict__ W1a)
{
    extern __shared__ __align__(16) char smag[];
    __nv_bfloat16* Whi = (__nv_bfloat16*)smag;
    __nv_bfloat16* Wlo = (__nv_bfloat16*)(smag + 18432);
    __nv_bfloat16* Ahi = (__nv_bfloat16*)(smag + 36864);
    __nv_bfloat16* Alo = (__nv_bfloat16*)(smag + 36864 + 18432);
    int* es = (int*)(smag + 73728);
    int* ss = (int*)(smag + 74240);
    int* ts = (int*)(smag + 74752);

    int tid = threadIdx.x;
    int lane = tid & 31, w = tid >> 5;

    // Stage W1a[:,64:] as split bf16, layout [n=128][k=64], row stride 72
    for (int idx = tid; idx < 128 * 64; idx += 256) {
        int c = idx >> 6, k = idx & 63;
        float x = W1a[c * 128 + 64 + k];
        __nv_bfloat16 h = __float2bfloat16_rn(x);
        Whi[c * 72 + k] = h;
        Wlo[c * 72 + k] = __float2bfloat16_rn(x - __bfloat162float(h));
    }

    int a_row = ((lane >> 3) & 1) * 8 + (lane & 7);
    int a_kof = ((lane >> 4) & 1) * 8;
    int b_n = lane & 7;
    int b_kof = ((lane >> 3) & 1) * 8;
    int rowb = w * 16;
    int r0 = lane >> 2, c2 = 2 * (lane & 3);
    const float4* attr4 = (const float4*)attr;
    float* S = (float*)(smag + 36864 + w * 4352);  // [16][68] per warp

    for (int t = blockIdx.x; t < NTILE; t += gridDim.x) {
        int base = t * 128;
        __syncthreads();  // S region (over A) free before restage
        if (tid < 128) {
            es[tid] = g_seid[base + tid];
            ss[tid] = g_ssrc[base + tid];
            ts[tid] = g_stgt[base + tid];
        }
        __syncthreads();
        // Gather 128 attr rows, split to bf16 hi/lo
        for (int i = tid; i < 2048; i += 256) {
            int r = i >> 4, q = i & 15;
            float4 v = attr4[(long long)es[r] * 16 + q];
            unsigned h01, l01, h23, l23;
            split2(v.x, v.y, h01, l01);
            split2(v.z, v.w, h23, l23);
            unsigned* dh = (unsigned*)(Ahi + r * 72 + 4 * q);
            unsigned* dl = (unsigned*)(Alo + r * 72 + 4 * q);
            dh[0] = h01; dh[1] = h23;
            dl[0] = l01; dl[1] = l23;
        }
        __syncthreads();

        float acc[16][4];
#pragma unroll
        for (int n = 0; n < 16; n++) {
            acc[n][0] = 0.f; acc[n][1] = 0.f; acc[n][2] = 0.f; acc[n][3] = 0.f;
        }

#pragma unroll
        for (int ks = 0; ks < 4; ks++) {
            unsigned ah0, ah1, ah2, ah3, al0, al1, al2, al3;
            const __nv_bfloat16* pa = Ahi + (rowb + a_row) * 72 + ks * 16 + a_kof;
            ldmx4(ah0, ah1, ah2, ah3, pa);
            const __nv_bfloat16* pl = Alo + (rowb + a_row) * 72 + ks * 16 + a_kof;
            ldmx4(al0, al1, al2, al3, pl);
#pragma unroll
            for (int nf = 0; nf < 16; nf++) {
                unsigned bh0, bh1, bl0, bl1;
                const __nv_bfloat16* pb = Whi + (8 * nf + b_n) * 72 + ks * 16 + b_kof;
                ldmx2(bh0, bh1, pb);
                const __nv_bfloat16* pbl = Wlo + (8 * nf + b_n) * 72 + ks * 16 + b_kof;
                ldmx2(bl0, bl1, pbl);
                mma_bf16(acc[nf], ah0, ah1, ah2, ah3, bh0, bh1);
                mma_bf16(acc[nf], ah0, ah1, ah2, ah3, bl0, bl1);
                mma_bf16(acc[nf], al0, al1, al2, al3, bh0, bh1);
            }
        }
        __syncthreads();  // A staging dead; S may overwrite

        int s0 = ss[rowb + r0], s1 = ss[rowb + r0 + 8];
#pragma unroll
        for (int h = 0; h < 2; h++) {
#pragma unroll
            for (int nq = 0; nq < 8; nq++) {
                int nf = 8 * h + nq;
                int gc = 8 * nf + c2;
                int lc = gc - 64 * h;
                float2 p0 = *(const float2*)&g_P[(long long)s0 * 128 + gc];
                float2 p1 = *(const float2*)&g_P[(long long)s1 * 128 + gc];
                float z0 = acc[nf][0] + p0.x; z0 = z0 >= 0.f ? z0 : 0.1f * z0;
                float z1 = acc[nf][1] + p0.y; z1 = z1 >= 0.f ? z1 : 0.1f * z1;
                float z2 = acc[nf][2] + p1.x; z2 = z2 >= 0.f ? z2 : 0.1f * z2;
                float z3 = acc[nf][3] + p1.y; z3 = z3 >= 0.f ? z3 : 0.1f * z3;
                *(float2*)&S[r0 * 68 + lc] = make_float2(z0, z1);
                *(float2*)&S[(r0 + 8) * 68 + lc] = make_float2(z2, z3);
            }
            __syncwarp();
            if (lane < 16) {
                int i = 0;
                while (i < 16) {
                    int tg = ts[rowb + i];
                    float4 s4 = make_float4(0.f, 0.f, 0.f, 0.f);
                    int jr = i;
                    do {
                        float4 v = *(const float4*)&S[jr * 68 + 4 * lane];
                        s4.x += v.x; s4.y += v.y; s4.z += v.z; s4.w += v.w;
                        jr++;
                    } while (jr < 16 && ts[rowb + jr] == tg);
                    atomicAdd((float4*)&g_AGG[(long long)tg * 128 + 64 * h + 4 * lane], s4);
                    i = jr;
                }
            }
            __syncwarp();
        }
    }
}

// FMA micro-tile: acc[4][4] += a[e].{x,y,z,w} * w{0..3}.{col}
#define FMA_TILE(acc, a0, a1, a2, a3, w0, w1, w2, w3)                          \
    {                                                                          \
        float4 _a[4] = {a0, a1, a2, a3};                                       \
        _Pragma("unroll") for (int _e = 0; _e < 4; _e++) {                     \
            acc[_e][0] += _a[_e].x * w0.x + _a[_e].y * w1.x +                  \
                          _a[_e].z * w2.x + _a[_e].w * w3.x;                   \
            acc[_e][1] += _a[_e].x * w0.y + _a[_e].y * w1.y +                  \
                          _a[_e].z * w2.y + _a[_e].w * w3.y;                   \
            acc[_e][2] += _a[_e].x * w0.z + _a[_e].y * w1.z +                  \
                          _a[_e].z * w2.z + _a[_e].w * w3.z;                   \
            acc[_e][3] += _a[_e].x * w0.w + _a[_e].y * w1.w +                  \
                          _a[_e].z * w2.w + _a[_e].w * w3.w;                   \
        }                                                                      \
    }

// ---------------------------------------------------------------------------
// Row GEMM: out[n][c] = in[n,:K] . W[c,:K] + bias.
// MODE 0: plain.  MODE 1: + cnt[n]*b, reads g_AGG and restores it to zero.
// MODE 2: plain + edge-histogram prologue (fused hist for launch-count).
// ---------------------------------------------------------------------------
template <int K, int MODE>
__global__ __launch_bounds__(256) void row_kernel(
    const float* __restrict__ in, const float* __restrict__ W,
    const float* __restrict__ bvec, float* __restrict__ out, int N,
    const int* __restrict__ eidx)
{
    if (MODE == 2) {
        int gidx = blockIdx.x * blockDim.x + threadIdx.x;
        for (int e = gidx; e < NEDGE; e += gridDim.x * blockDim.x)
            atomicAdd(&g_hist[eidx[NEDGE + e]], 1);
    }
    extern __shared__ __align__(16) float smrow[];
    constexpr int K4 = K / 4;
    float* Wt = smrow;               // [K][128]
    float* in_s = smrow + K * 128;   // [32][K]
    int tid = threadIdx.x;
    int j = tid & 31, m = tid >> 5;

    for (int idx = tid; idx < K * 128; idx += 256) {
        int k = idx % K, c = idx / K;
        Wt[k * 128 + c] = W[c * 128 + k];
    }
    __syncthreads();

    float4 b4 = *(const float4*)&bvec[4 * j];
    const float4* Wt4 = (const float4*)Wt;
    const float4* is4 = (const float4*)in_s;
    int nt = (N + 31) >> 5;

    for (int t = blockIdx.x; t < nt; t += gridDim.x) {
        int base = t * 32;
        for (int idx = tid; idx < 32 * K4; idx += 256) {
            int r = idx / K4, kq = idx % K4;
            int rg = base + r; if (rg > N - 1) rg = N - 1;
            ((float4*)in_s)[idx] = ((const float4*)in)[(long long)rg * K4 + kq];
        }
        __syncthreads();
        if (MODE == 1) {
            // Restore g_AGG to zero for the next graph replay (each row is
            // owned by exactly one tile; clamped duplicates rewrite zero).
            float4 z = make_float4(0.f, 0.f, 0.f, 0.f);
            for (int idx = tid; idx < 32 * K4; idx += 256) {
                int r = idx / K4, kq = idx % K4;
                int rg = base + r; if (rg > N - 1) rg = N - 1;
                ((float4*)g_AGG)[(long long)rg * K4 + kq] = z;
            }
        }

        float acc[4][4] = {};
#pragma unroll 8
        for (int k4 = 0; k4 < K4; k4++) {
            float4 a0 = is4[(4 * m + 0) * K4 + k4];
            float4 a1 = is4[(4 * m + 1) * K4 + k4];
            float4 a2 = is4[(4 * m + 2) * K4 + k4];
            float4 a3 = is4[(4 * m + 3) * K4 + k4];
            float4 w0 = Wt4[(4 * k4 + 0) * 32 + j];
            float4 w1 = Wt4[(4 * k4 + 1) * 32 + j];
            float4 w2 = Wt4[(4 * k4 + 2) * 32 + j];
            float4 w3 = Wt4[(4 * k4 + 3) * 32 + j];
            FMA_TILE(acc, a0, a1, a2, a3, w0, w1, w2, w3)
        }
#pragma unroll
        for (int e = 0; e < 4; e++) {
            int r = base + 4 * m + e;
            if (r < N) {
                float sc = (MODE == 1) ? g_CNT[r] : 1.f;
                float4 v;
                v.x = acc[e][0] + sc * b4.x;
                v.y = acc[e][1] + sc * b4.y;
                v.z = acc[e][2] + sc * b4.z;
                v.w = acc[e][3] + sc * b4.w;
                *(float4*)&out[(long long)r * 128 + 4 * j] = v;
            }
        }
        __syncthreads();
    }
}

// ---------------------------------------------------------------------------
// Node MLP hidden: H = leaky([x_g | A | u[batch]] @ W2a^T + b2a), K = 320.
// ---------------------------------------------------------------------------
__global__ __launch_bounds__(256) void nodeH_kernel(
    const float* __restrict__ xg, const float* __restrict__ u,
    const int* __restrict__ batch, const float* __restrict__ W2a,
    const float* __restrict__ b2a, int N)
{
    extern __shared__ __align__(16) float smnh[];
    float* Wt = smnh;                 // [320][128]
    float* in_s = smnh + 320 * 128;   // [32][320]
    int tid = threadIdx.x;
    int j = tid & 31, m = tid >> 5;

    for (int idx = tid; idx < 320 * 128; idx += 256) {
        int k = idx % 320, c = idx / 320;
        Wt[k * 128 + c] = W2a[c * 320 + k];
    }
    __syncthreads();

    float4 b4 = *(const float4*)&b2a[4 * j];
    const float4* Wt4 = (const float4*)Wt;
    const float4* is4 = (const float4*)in_s;
    int nt = (N + 31) >> 5;

    for (int t = blockIdx.x; t < nt; t += gridDim.x) {
        int base = t * 32;
        for (int idx = tid; idx < 32 * 80; idx += 256) {
            int r = idx / 80, q = idx % 80;
            int rg = base + r; if (rg > N - 1) rg = N - 1;
            float4 v;
            if (q < 32)      v = ((const float4*)xg)[(long long)rg * 32 + q];
            else if (q < 64) v = ((const float4*)g_A)[(long long)rg * 32 + (q - 32)];
            else             v = ((const float4*)u)[batch[rg] * 16 + (q - 64)];
            ((float4*)in_s)[idx] = v;
        }
        __syncthreads();

        float acc[4][4] = {};
#pragma unroll 8
        for (int k4 = 0; k4 < 80; k4++) {
            float4 a0 = is4[(4 * m + 0) * 80 + k4];
            float4 a1 = is4[(4 * m + 1) * 80 + k4];
            float4 a2 = is4[(4 * m + 2) * 80 + k4];
            float4 a3 = is4[(4 * m + 3) * 80 + k4];
            float4 w0 = Wt4[(4 * k4 + 0) * 32 + j];
            float4 w1 = Wt4[(4 * k4 + 1) * 32 + j];
            float4 w2 = Wt4[(4 * k4 + 2) * 32 + j];
            float4 w3 = Wt4[(4 * k4 + 3) * 32 + j];
            FMA_TILE(acc, a0, a1, a2, a3, w0, w1, w2, w3)
        }
#pragma unroll
        for (int e = 0; e < 4; e++) {
            int r = base + 4 * m + e;
            if (r < N) {
                float4 v;
                v.x = acc[e][0] + b4.x; v.x = v.x >= 0.f ? v.x : 0.1f * v.x;
                v.y = acc[e][1] + b4.y; v.y = v.y >= 0.f ? v.y : 0.1f * v.y;
                v.z = acc[e][2] + b4.z; v.z = v.z >= 0.f ? v.z : 0.1f * v.z;
                v.w = acc[e][3] + b4.w; v.w = v.w >= 0.f ? v.w : 0.1f * v.w;
                *(float4*)&g_H[(long long)r * 128 + 4 * j] = v;
            }
        }
        __syncthreads();
    }
}

extern "C" void kernel_launch(void* const* d_in, const int* in_sizes, int n_in,
                              void* d_out, int out_size)
{
    const float* x_h = (const float*)d_in[0];
    const float* x_g = (const float*)d_in[1];
    const float* eattr = (const float*)d_in[2];
    const float* u = (const float*)d_in[3];
    const float* W1a = (const float*)d_in[4];
    const float* b1a = (const float*)d_in[5];
    const float* W1b = (const float*)d_in[6];
    const float* b1b = (const float*)d_in[7];
    const float* W2a = (const float*)d_in[8];
    const float* b2a = (const float*)d_in[9];
    const float* W2b = (const float*)d_in[10];
    const float* b2b = (const float*)d_in[11];
    const int* eidx = (const int*)d_in[12];   // int32
    const int* batch = (const int*)d_in[13];  // int32
    float* out = (float*)d_out;

    float *pP, *pAGG, *pA, *pH;
    cudaGetSymbolAddress((void**)&pP, g_P);
    cudaGetSymbolAddress((void**)&pAGG, g_AGG);
    cudaGetSymbolAddress((void**)&pA, g_A);
    cudaGetSymbolAddress((void**)&pH, g_H);

    size_t smem64 = (size_t)(64 * 128 + 32 * 64) * 4;
    size_t smem128 = (size_t)(128 * 128 + 32 * 128) * 4;
    size_t smem320 = (size_t)(320 * 128 + 32 * 320) * 4;
    size_t smem_agg = 75264;
    cudaFuncSetAttribute(row_kernel<64, 2>,
                         cudaFuncAttributeMaxDynamicSharedMemorySize, (int)smem64);
    cudaFuncSetAttribute(row_kernel<128, 1>,
                         cudaFuncAttributeMaxDynamicSharedMemorySize, (int)smem128);
    cudaFuncSetAttribute(row_kernel<128, 0>,
                         cudaFuncAttributeMaxDynamicSharedMemorySize, (int)smem128);
    cudaFuncSetAttribute(nodeH_kernel,
                         cudaFuncAttributeMaxDynamicSharedMemorySize, (int)smem320);
    cudaFuncSetAttribute(agg_kernel,
                         cudaFuncAttributeMaxDynamicSharedMemorySize, (int)smem_agg);

    // 1: P = x_h @ W1a[:, :64]^T + b1a  (+ fused edge histogram)
    row_kernel<64, 2><<<1563, 256, smem64>>>(x_h, W1a, b1a, pP, NHN, eidx);
    // 2: scan (reads + re-zeroes hist; emits off/cursor/CNT)
    scan_kernel<<<1, 1024>>>();
    // 3: counting-sort permute
    permute_kernel<<<1184, 256>>>(eidx);
    // 4: aggregation (PROFILED LAUNCH)
    agg_kernel<<<296, 256, smem_agg>>>(eattr, W1a);
    // 5: A = AGG @ W1b^T + cnt * b1b  (reads + re-zeroes AGG)
    row_kernel<128, 1><<<1563, 256, smem128>>>(pAGG, W1b, b1b, pA, NGN, nullptr);
    // 6: H = leaky([x_g | A | u[batch]] @ W2a^T + b2a)
    nodeH_kernel<<<1563, 256, smem320>>>(x_g, u, batch, W2a, b2a, NGN);
    // 7: out = H @ W2b^T + b2b
    row_kernel<128, 0><<<1563, 256, smem128>>>(pH, W2b, b2b, out, NGN, nullptr);
}

// round 13
// speedup vs baseline: 1.7334x; 1.2675x over previous
#include <cuda_runtime.h>
#include <cuda_bf16.h>
#include <cstdint>

#define NHN 50000
#define NGN 50000
#define NEDGE 1600000
#define NTILE (NEDGE / 128)

// Scratch (static __device__ arrays: allocation-free per harness rules).
// Zero-state protocol: g_hist and g_AGG start zero (static init) and every
// consumer restores them to zero after reading, so each graph replay sees
// identical starting state.
__device__ float g_P[NHN * 128];    // x_h @ W1a[:, :64]^T + b1a
__device__ float g_AGG[NGN * 128];  // per-target sum of leaky(z_e)
__device__ float g_CNT[NGN];        // edge count per target node
__device__ float g_A[NGN * 128];    // AGG @ W1b^T + cnt*b1b
__device__ float g_H[NGN * 128];    // hidden of node MLP
__device__ int g_hist[NGN];
__device__ int g_off[NGN + 1];
__device__ int g_cursor[NGN];
__device__ int g_seid[NEDGE];  // edge ids sorted by target
__device__ int g_ssrc[NEDGE];  // src ids sorted by target
__device__ int g_stgt[NEDGE];  // tgt ids sorted (nondecreasing)

// Warp-shuffle block scan over 50K bins, 3 barriers per 1024-block.
// Reads g_hist and restores it to zero; emits off, cursor, float CNT.
__global__ __launch_bounds__(1024) void scan_kernel() {
    __shared__ int wsum[32];
    __shared__ int carry_s;
    int tid = threadIdx.x;
    int lane = tid & 31, wid = tid >> 5;
    if (tid == 0) carry_s = 0;
    __syncthreads();
    for (int base = 0; base < NGN; base += 1024) {
        int i = base + tid;
        int orig = (i < NGN) ? g_hist[i] : 0;
        if (i < NGN) g_hist[i] = 0;  // restore for next replay
        int v = orig;
#pragma unroll
        for (int d = 1; d < 32; d <<= 1) {
            int t = __shfl_up_sync(0xFFFFFFFFu, v, d);
            if (lane >= d) v += t;
        }
        if (lane == 31) wsum[wid] = v;
        __syncthreads();
        if (wid == 0) {
            int s = wsum[lane];
#pragma unroll
            for (int d = 1; d < 32; d <<= 1) {
                int t = __shfl_up_sync(0xFFFFFFFFu, s, d);
                if (lane >= d) s += t;
            }
            wsum[lane] = s;
        }
        __syncthreads();
        int carry = carry_s;
        int incl = v + (wid ? wsum[wid - 1] : 0);
        if (i < NGN) {
            int excl = carry + incl - orig;
            g_off[i] = excl;
            g_cursor[i] = excl;
            g_CNT[i] = (float)orig;
        }
        __syncthreads();
        if (tid == 0) carry_s = carry + wsum[31];
        __syncthreads();
    }
    if (tid == 0) g_off[NGN] = carry_s;
}

__global__ void permute_kernel(const int* __restrict__ eidx) {
    int idx = blockIdx.x * blockDim.x + threadIdx.x;
    for (int e = idx; e < NEDGE; e += gridDim.x * blockDim.x) {
        int t = eidx[NEDGE + e];
        int pos = atomicAdd(&g_cursor[t], 1);
        g_seid[pos] = e;
        g_ssrc[pos] = eidx[e];
        g_stgt[pos] = t;
    }
}

// ---------------- mma / ldmatrix helpers ----------------
__device__ __forceinline__ void ldmx4(unsigned& r0, unsigned& r1, unsigned& r2,
                                      unsigned& r3, const void* p) {
    unsigned a = (unsigned)__cvta_generic_to_shared(p);
    asm volatile("ldmatrix.sync.aligned.m8n8.x4.shared.b16 {%0,%1,%2,%3}, [%4];"
                 : "=r"(r0), "=r"(r1), "=r"(r2), "=r"(r3) : "r"(a));
}
__device__ __forceinline__ void mma_bf16(float* d, unsigned a0, unsigned a1,
                                         unsigned a2, unsigned a3,
                                         unsigned b0, unsigned b1) {
    asm volatile(
        "mma.sync.aligned.m16n8k16.row.col.f32.bf16.bf16.f32 "
        "{%0,%1,%2,%3}, {%4,%5,%6,%7}, {%8,%9}, {%0,%1,%2,%3};"
        : "+f"(d[0]), "+f"(d[1]), "+f"(d[2]), "+f"(d[3])
        : "r"(a0), "r"(a1), "r"(a2), "r"(a3), "r"(b0), "r"(b1));
}
__device__ __forceinline__ void split2(float x, float y, unsigned& hi, unsigned& lo) {
    __nv_bfloat16 hx = __float2bfloat16_rn(x), hy = __float2bfloat16_rn(y);
    __nv_bfloat16 lx = __float2bfloat16_rn(x - __bfloat162float(hx));
    __nv_bfloat16 ly = __float2bfloat16_rn(y - __bfloat162float(hy));
    __nv_bfloat162 h2, l2;
    h2.x = hx; h2.y = hy; l2.x = lx; l2.y = ly;
    hi = *(unsigned*)&h2;
    lo = *(unsigned*)&l2;
}

// SMEM layout for agg (bytes from dynamic base)
#define SMA_WHI 0
#define SMA_WLO 18432
#define SMA_AHI 36864
#define SMA_ALO 55296
#define SMA_S   73728              // 8 warps x [16][68] f32 = 34816
#define SMA_IDX 108544             // 3 x 128 int = 1536
#define SMA_TOTAL 110080

// ---------------------------------------------------------------------------
// Tensor-core aggregation over flat tiles of 128 sorted edges (mma.sync —
// tcgen05 unavailable: harness PTX targets compute_103, no 'a' features).
// Z = attr_tile @ W1a_x^T via 3-pass split-bf16 mma, processed in two 64-col
// halves (acc[8][4] = 32 regs -> 2 CTAs/SM); B fragments loaded as ldmx4
// pairs. Epilogue per half: + P[src] fp32, leaky, per-warp segmented reduce
// over sorted targets, float4 atomics.
// ---------------------------------------------------------------------------
__global__ __launch_bounds__(256, 2) void agg_kernel(
    const float* __restrict__ attr, const float* __restrict__ W1a)
{
    extern __shared__ __align__(16) char smag[];
    __nv_bfloat16* Whi = (__nv_bfloat16*)(smag + SMA_WHI);
    __nv_bfloat16* Wlo = (__nv_bfloat16*)(smag + SMA_WLO);
    __nv_bfloat16* Ahi = (__nv_bfloat16*)(smag + SMA_AHI);
    __nv_bfloat16* Alo = (__nv_bfloat16*)(smag + SMA_ALO);
    int* es = (int*)(smag + SMA_IDX);
    int* ss = es + 128;
    int* ts = ss + 128;

    int tid = threadIdx.x;
    int lane = tid & 31, w = tid >> 5;

    // Stage W1a[:,64:] as split bf16, layout [n=128][k=64], row stride 72
    for (int idx = tid; idx < 128 * 64; idx += 256) {
        int c = idx >> 6, k = idx & 63;
        float x = W1a[c * 128 + 64 + k];
        __nv_bfloat16 h = __float2bfloat16_rn(x);
        Whi[c * 72 + k] = h;
        Wlo[c * 72 + k] = __float2bfloat16_rn(x - __bfloat162float(h));
    }

    int a_row = ((lane >> 3) & 1) * 8 + (lane & 7);
    int a_kof = ((lane >> 4) & 1) * 8;
    // B ldmx4 pair mapping: covers n-frags np and np+1
    int b_pair_off = 8 * ((lane >> 4) & 1) + (lane & 7);
    int b_kof = ((lane >> 3) & 1) * 8;
    int rowb = w * 16;
    int r0 = lane >> 2, c2 = 2 * (lane & 3);
    const float4* attr4 = (const float4*)attr;
    float* S = (float*)(smag + SMA_S) + w * 1088;  // [16][68] per warp

    for (int t = blockIdx.x; t < NTILE; t += gridDim.x) {
        int base = t * 128;
        __syncthreads();  // previous tile fully consumed
        if (tid < 128) {
            es[tid] = g_seid[base + tid];
            ss[tid] = g_ssrc[base + tid];
            ts[tid] = g_stgt[base + tid];
        }
        __syncthreads();
        // Gather 128 attr rows, split to bf16 hi/lo
        for (int i = tid; i < 2048; i += 256) {
            int r = i >> 4, q = i & 15;
            float4 v = attr4[(long long)es[r] * 16 + q];
            unsigned h01, l01, h23, l23;
            split2(v.x, v.y, h01, l01);
            split2(v.z, v.w, h23, l23);
            unsigned* dh = (unsigned*)(Ahi + r * 72 + 4 * q);
            unsigned* dl = (unsigned*)(Alo + r * 72 + 4 * q);
            dh[0] = h01; dh[1] = h23;
            dl[0] = l01; dl[1] = l23;
        }
        __syncthreads();

        int s0 = ss[rowb + r0], s1 = ss[rowb + r0 + 8];

#pragma unroll
        for (int half = 0; half < 2; half++) {
            float acc[8][4];
#pragma unroll
            for (int n = 0; n < 8; n++) {
                acc[n][0] = 0.f; acc[n][1] = 0.f;
                acc[n][2] = 0.f; acc[n][3] = 0.f;
            }

#pragma unroll
            for (int ks = 0; ks < 4; ks++) {
                unsigned ah0, ah1, ah2, ah3, al0, al1, al2, al3;
                const __nv_bfloat16* pa = Ahi + (rowb + a_row) * 72 + ks * 16 + a_kof;
                ldmx4(ah0, ah1, ah2, ah3, pa);
                const __nv_bfloat16* pl = Alo + (rowb + a_row) * 72 + ks * 16 + a_kof;
                ldmx4(al0, al1, al2, al3, pl);
#pragma unroll
                for (int np = 0; np < 8; np += 2) {
                    int nf = half * 8 + np;
                    unsigned bh0, bh1, bh2, bh3, bl0, bl1, bl2, bl3;
                    const __nv_bfloat16* pbh =
                        Whi + (8 * nf + b_pair_off) * 72 + ks * 16 + b_kof;
                    ldmx4(bh0, bh1, bh2, bh3, pbh);
                    const __nv_bfloat16* pbl =
                        Wlo + (8 * nf + b_pair_off) * 72 + ks * 16 + b_kof;
                    ldmx4(bl0, bl1, bl2, bl3, pbl);
                    mma_bf16(acc[np], ah0, ah1, ah2, ah3, bh0, bh1);
                    mma_bf16(acc[np], ah0, ah1, ah2, ah3, bl0, bl1);
                    mma_bf16(acc[np], al0, al1, al2, al3, bh0, bh1);
                    mma_bf16(acc[np + 1], ah0, ah1, ah2, ah3, bh2, bh3);
                    mma_bf16(acc[np + 1], ah0, ah1, ah2, ah3, bl2, bl3);
                    mma_bf16(acc[np + 1], al0, al1, al2, al3, bh2, bh3);
                }
            }

            // Epilogue for this 64-col half
#pragma unroll
            for (int nq = 0; nq < 8; nq++) {
                int gc = 64 * half + 8 * nq + c2;
                int lc = 8 * nq + c2;
                float2 p0 = *(const float2*)&g_P[(long long)s0 * 128 + gc];
                float2 p1 = *(const float2*)&g_P[(long long)s1 * 128 + gc];
                float z0 = acc[nq][0] + p0.x; z0 = z0 >= 0.f ? z0 : 0.1f * z0;
                float z1 = acc[nq][1] + p0.y; z1 = z1 >= 0.f ? z1 : 0.1f * z1;
                float z2 = acc[nq][2] + p1.x; z2 = z2 >= 0.f ? z2 : 0.1f * z2;
                float z3 = acc[nq][3] + p1.y; z3 = z3 >= 0.f ? z3 : 0.1f * z3;
                *(float2*)&S[r0 * 68 + lc] = make_float2(z0, z1);
                *(float2*)&S[(r0 + 8) * 68 + lc] = make_float2(z2, z3);
            }
            __syncwarp();
            if (lane < 16) {
                int i = 0;
                while (i < 16) {
                    int tg = ts[rowb + i];
                    float4 s4 = make_float4(0.f, 0.f, 0.f, 0.f);
                    int jr = i;
                    do {
                        float4 v = *(const float4*)&S[jr * 68 + 4 * lane];
                        s4.x += v.x; s4.y += v.y; s4.z += v.z; s4.w += v.w;
                        jr++;
                    } while (jr < 16 && ts[rowb + jr] == tg);
                    atomicAdd((float4*)&g_AGG[(long long)tg * 128 + 64 * half + 4 * lane], s4);
                    i = jr;
                }
            }
            __syncwarp();
        }
    }
}

// FMA micro-tile: acc[4][4] += a[e].{x,y,z,w} * w{0..3}.{col}
#define FMA_TILE(acc, a0, a1, a2, a3, w0, w1, w2, w3)                          \
    {                                                                          \
        float4 _a[4] = {a0, a1, a2, a3};                                       \
        _Pragma("unroll") for (int _e = 0; _e < 4; _e++) {                     \
            acc[_e][0] += _a[_e].x * w0.x + _a[_e].y * w1.x +                  \
                          _a[_e].z * w2.x + _a[_e].w * w3.x;                   \
            acc[_e][1] += _a[_e].x * w0.y + _a[_e].y * w1.y +                  \
                          _a[_e].z * w2.y + _a[_e].w * w3.y;                   \
            acc[_e][2] += _a[_e].x * w0.z + _a[_e].y * w1.z +                  \
                          _a[_e].z * w2.z + _a[_e].w * w3.z;                   \
            acc[_e][3] += _a[_e].x * w0.w + _a[_e].y * w1.w +                  \
                          _a[_e].z * w2.w + _a[_e].w * w3.w;                   \
        }                                                                      \
    }

// ---------------------------------------------------------------------------
// Row GEMM: out[n][c] = in[n,:K] . W[c,:K] + bias.
// MODE 0: plain.  MODE 1: + cnt[n]*b, reads g_AGG and restores it to zero.
// MODE 2: plain + edge-histogram prologue (fused hist for launch-count).
// ---------------------------------------------------------------------------
template <int K, int MODE>
__global__ __launch_bounds__(256) void row_kernel(
    const float* __restrict__ in, const float* __restrict__ W,
    const float* __restrict__ bvec, float* __restrict__ out, int N,
    const int* __restrict__ eidx)
{
    if (MODE == 2) {
        int gidx = blockIdx.x * blockDim.x + threadIdx.x;
        for (int e = gidx; e < NEDGE; e += gridDim.x * blockDim.x)
            atomicAdd(&g_hist[eidx[NEDGE + e]], 1);
    }
    extern __shared__ __align__(16) float smrow[];
    constexpr int K4 = K / 4;
    float* Wt = smrow;               // [K][128]
    float* in_s = smrow + K * 128;   // [32][K]
    int tid = threadIdx.x;
    int j = tid & 31, m = tid >> 5;

    for (int idx = tid; idx < K * 128; idx += 256) {
        int k = idx % K, c = idx / K;
        Wt[k * 128 + c] = W[c * 128 + k];
    }
    __syncthreads();

    float4 b4 = *(const float4*)&bvec[4 * j];
    const float4* Wt4 = (const float4*)Wt;
    const float4* is4 = (const float4*)in_s;
    int nt = (N + 31) >> 5;

    for (int t = blockIdx.x; t < nt; t += gridDim.x) {
        int base = t * 32;
        for (int idx = tid; idx < 32 * K4; idx += 256) {
            int r = idx / K4, kq = idx % K4;
            int rg = base + r; if (rg > N - 1) rg = N - 1;
            ((float4*)in_s)[idx] = ((const float4*)in)[(long long)rg * K4 + kq];
        }
        __syncthreads();
        if (MODE == 1) {
            // Restore g_AGG to zero for the next graph replay (each row is
            // owned by exactly one tile; clamped duplicates rewrite zero).
            float4 z = make_float4(0.f, 0.f, 0.f, 0.f);
            for (int idx = tid; idx < 32 * K4; idx += 256) {
                int r = idx / K4, kq = idx % K4;
                int rg = base + r; if (rg > N - 1) rg = N - 1;
                ((float4*)g_AGG)[(long long)rg * K4 + kq] = z;
            }
        }

        float acc[4][4] = {};
#pragma unroll 8
        for (int k4 = 0; k4 < K4; k4++) {
            float4 a0 = is4[(4 * m + 0) * K4 + k4];
            float4 a1 = is4[(4 * m + 1) * K4 + k4];
            float4 a2 = is4[(4 * m + 2) * K4 + k4];
            float4 a3 = is4[(4 * m + 3) * K4 + k4];
            float4 w0 = Wt4[(4 * k4 + 0) * 32 + j];
            float4 w1 = Wt4[(4 * k4 + 1) * 32 + j];
            float4 w2 = Wt4[(4 * k4 + 2) * 32 + j];
            float4 w3 = Wt4[(4 * k4 + 3) * 32 + j];
            FMA_TILE(acc, a0, a1, a2, a3, w0, w1, w2, w3)
        }
#pragma unroll
        for (int e = 0; e < 4; e++) {
            int r = base + 4 * m + e;
            if (r < N) {
                float sc = (MODE == 1) ? g_CNT[r] : 1.f;
                float4 v;
                v.x = acc[e][0] + sc * b4.x;
                v.y = acc[e][1] + sc * b4.y;
                v.z = acc[e][2] + sc * b4.z;
                v.w = acc[e][3] + sc * b4.w;
                *(float4*)&out[(long long)r * 128 + 4 * j] = v;
            }
        }
        __syncthreads();
    }
}

// ---------------------------------------------------------------------------
// Node MLP hidden: H = leaky([x_g | A | u[batch]] @ W2a^T + b2a), K = 320.
// ---------------------------------------------------------------------------
__global__ __launch_bounds__(256) void nodeH_kernel(
    const float* __restrict__ xg, const float* __restrict__ u,
    const int* __restrict__ batch, const float* __restrict__ W2a,
    const float* __restrict__ b2a, int N)
{
    extern __shared__ __align__(16) float smnh[];
    float* Wt = smnh;                 // [320][128]
    float* in_s = smnh + 320 * 128;   // [32][320]
    int tid = threadIdx.x;
    int j = tid & 31, m = tid >> 5;

    for (int idx = tid; idx < 320 * 128; idx += 256) {
        int k = idx % 320, c = idx / 320;
        Wt[k * 128 + c] = W2a[c * 320 + k];
    }
    __syncthreads();

    float4 b4 = *(const float4*)&b2a[4 * j];
    const float4* Wt4 = (const float4*)Wt;
    const float4* is4 = (const float4*)in_s;
    int nt = (N + 31) >> 5;

    for (int t = blockIdx.x; t < nt; t += gridDim.x) {
        int base = t * 32;
        for (int idx = tid; idx < 32 * 80; idx += 256) {
            int r = idx / 80, q = idx % 80;
            int rg = base + r; if (rg > N - 1) rg = N - 1;
            float4 v;
            if (q < 32)      v = ((const float4*)xg)[(long long)rg * 32 + q];
            else if (q < 64) v = ((const float4*)g_A)[(long long)rg * 32 + (q - 32)];
            else             v = ((const float4*)u)[batch[rg] * 16 + (q - 64)];
            ((float4*)in_s)[idx] = v;
        }
        __syncthreads();

        float acc[4][4] = {};
#pragma unroll 8
        for (int k4 = 0; k4 < 80; k4++) {
            float4 a0 = is4[(4 * m + 0) * 80 + k4];
            float4 a1 = is4[(4 * m + 1) * 80 + k4];
            float4 a2 = is4[(4 * m + 2) * 80 + k4];
            float4 a3 = is4[(4 * m + 3) * 80 + k4];
            float4 w0 = Wt4[(4 * k4 + 0) * 32 + j];
            float4 w1 = Wt4[(4 * k4 + 1) * 32 + j];
            float4 w2 = Wt4[(4 * k4 + 2) * 32 + j];
            float4 w3 = Wt4[(4 * k4 + 3) * 32 + j];
            FMA_TILE(acc, a0, a1, a2, a3, w0, w1, w2, w3)
        }
#pragma unroll
        for (int e = 0; e < 4; e++) {
            int r = base + 4 * m + e;
            if (r < N) {
                float4 v;
                v.x = acc[e][0] + b4.x; v.x = v.x >= 0.f ? v.x : 0.1f * v.x;
                v.y = acc[e][1] + b4.y; v.y = v.y >= 0.f ? v.y : 0.1f * v.y;
                v.z = acc[e][2] + b4.z; v.z = v.z >= 0.f ? v.z : 0.1f * v.z;
                v.w = acc[e][3] + b4.w; v.w = v.w >= 0.f ? v.w : 0.1f * v.w;
                *(float4*)&g_H[(long long)r * 128 + 4 * j] = v;
            }
        }
        __syncthreads();
    }
}

extern "C" void kernel_launch(void* const* d_in, const int* in_sizes, int n_in,
                              void* d_out, int out_size)
{
    const float* x_h = (const float*)d_in[0];
    const float* x_g = (const float*)d_in[1];
    const float* eattr = (const float*)d_in[2];
    const float* u = (const float*)d_in[3];
    const float* W1a = (const float*)d_in[4];
    const float* b1a = (const float*)d_in[5];
    const float* W1b = (const float*)d_in[6];
    const float* b1b = (const float*)d_in[7];
    const float* W2a = (const float*)d_in[8];
    const float* b2a = (const float*)d_in[9];
    const float* W2b = (const float*)d_in[10];
    const float* b2b = (const float*)d_in[11];
    const int* eidx = (const int*)d_in[12];   // int32
    const int* batch = (const int*)d_in[13];  // int32
    float* out = (float*)d_out;

    float *pP, *pAGG, *pA, *pH;
    cudaGetSymbolAddress((void**)&pP, g_P);
    cudaGetSymbolAddress((void**)&pAGG, g_AGG);
    cudaGetSymbolAddress((void**)&pA, g_A);
    cudaGetSymbolAddress((void**)&pH, g_H);

    size_t smem64 = (size_t)(64 * 128 + 32 * 64) * 4;
    size_t smem128 = (size_t)(128 * 128 + 32 * 128) * 4;
    size_t smem320 = (size_t)(320 * 128 + 32 * 320) * 4;
    cudaFuncSetAttribute(row_kernel<64, 2>,
                         cudaFuncAttributeMaxDynamicSharedMemorySize, (int)smem64);
    cudaFuncSetAttribute(row_kernel<128, 1>,
                         cudaFuncAttributeMaxDynamicSharedMemorySize, (int)smem128);
    cudaFuncSetAttribute(row_kernel<128, 0>,
                         cudaFuncAttributeMaxDynamicSharedMemorySize, (int)smem128);
    cudaFuncSetAttribute(nodeH_kernel,
                         cudaFuncAttributeMaxDynamicSharedMemorySize, (int)smem320);
    cudaFuncSetAttribute(agg_kernel,
                         cudaFuncAttributeMaxDynamicSharedMemorySize, SMA_TOTAL);

    // 1: P = x_h @ W1a[:, :64]^T + b1a  (+ fused edge histogram)
    row_kernel<64, 2><<<1563, 256, smem64>>>(x_h, W1a, b1a, pP, NHN, eidx);
    // 2: scan (reads + re-zeroes hist; emits off/cursor/CNT)
    scan_kernel<<<1, 1024>>>();
    // 3: counting-sort permute
    permute_kernel<<<1184, 256>>>(eidx);
    // 4: aggregation (PROFILED LAUNCH)
    agg_kernel<<<296, 256, SMA_TOTAL>>>(eattr, W1a);
    // 5: A = AGG @ W1b^T + cnt * b1b  (reads + re-zeroes AGG)
    row_kernel<128, 1><<<1563, 256, smem128>>>(pAGG, W1b, b1b, pA, NGN, nullptr);
    // 6: H = leaky([x_g | A | u[batch]] @ W2a^T + b2a)
    nodeH_kernel<<<1563, 256, smem320>>>(x_g, u, batch, W2a, b2a, NGN);
    // 7: out = H @ W2b^T + b2b
    row_kernel<128, 0><<<1563, 256, smem128>>>(pH, W2b, b2b, out, NGN, nullptr);
}

// round 16
// speedup vs baseline: 1.9323x; 1.1148x over previous
#include <cuda_runtime.h>
#include <cuda_bf16.h>
#include <cstdint>

#define NHN 50000
#define NGN 50000
#define NEDGE 1600000
#define NTILE (NEDGE / 128)

// Scratch (static __device__ arrays: allocation-free per harness rules).
// Zero-state protocol: g_hist and g_AGG start zero (static init) and every
// consumer restores them to zero after reading, so each graph replay sees
// identical starting state.
__device__ float g_P[NHN * 128];    // x_h @ W1a[:, :64]^T + b1a
__device__ float g_AGG[NGN * 128];  // per-target sum of leaky(z_e)
__device__ float g_CNT[NGN];        // edge count per target node
__device__ float g_H[NGN * 128];    // hidden of node MLP
__device__ float g_Wcomb[128 * 128];// W2a[:,128:256] @ W1b
__device__ float g_v[128];          // W2a[:,128:256] @ b1b
__device__ float g_U16[16 * 128];   // u @ W2a[:,256:]^T + b2a
__device__ int g_hist[NGN];
__device__ int g_off[NGN + 1];
__device__ int g_cursor[NGN];
__device__ int g_seid[NEDGE];  // edge ids sorted by target
__device__ int g_ssrc[NEDGE];  // src ids sorted by target
__device__ int g_stgt[NEDGE];  // tgt ids sorted (nondecreasing)

// Warp-shuffle block scan over 50K bins, 3 barriers per 1024-block.
// Reads g_hist and restores it to zero; emits off, cursor, float CNT.
__global__ __launch_bounds__(1024) void scan_kernel() {
    __shared__ int wsum[32];
    __shared__ int carry_s;
    int tid = threadIdx.x;
    int lane = tid & 31, wid = tid >> 5;
    if (tid == 0) carry_s = 0;
    __syncthreads();
    for (int base = 0; base < NGN; base += 1024) {
        int i = base + tid;
        int orig = (i < NGN) ? g_hist[i] : 0;
        if (i < NGN) g_hist[i] = 0;  // restore for next replay
        int v = orig;
#pragma unroll
        for (int d = 1; d < 32; d <<= 1) {
            int t = __shfl_up_sync(0xFFFFFFFFu, v, d);
            if (lane >= d) v += t;
        }
        if (lane == 31) wsum[wid] = v;
        __syncthreads();
        if (wid == 0) {
            int s = wsum[lane];
#pragma unroll
            for (int d = 1; d < 32; d <<= 1) {
                int t = __shfl_up_sync(0xFFFFFFFFu, s, d);
                if (lane >= d) s += t;
            }
            wsum[lane] = s;
        }
        __syncthreads();
        int carry = carry_s;
        int incl = v + (wid ? wsum[wid - 1] : 0);
        if (i < NGN) {
            int excl = carry + incl - orig;
            g_off[i] = excl;
            g_cursor[i] = excl;
            g_CNT[i] = (float)orig;
        }
        __syncthreads();
        if (tid == 0) carry_s = carry + wsum[31];
        __syncthreads();
    }
    if (tid == 0) g_off[NGN] = carry_s;
}

__global__ void permute_kernel(const int* __restrict__ eidx) {
    int idx = blockIdx.x * blockDim.x + threadIdx.x;
    for (int e = idx; e < NEDGE; e += gridDim.x * blockDim.x) {
        int t = eidx[NEDGE + e];
        int pos = atomicAdd(&g_cursor[t], 1);
        g_seid[pos] = e;
        g_ssrc[pos] = eidx[e];
        g_stgt[pos] = t;
    }
}

// Fold the linear A-step into nodeH:
//   blocks 0..127: Wcomb[c][k] = sum_j W2a[c][128+j]*W1b[j][k]; v[c] = sum_j W2a[c][128+j]*b1b[j]
//   blocks 128..143: U16[g][c] = sum_q W2a[c][256+q]*u[g][q] + b2a[c]
__global__ __launch_bounds__(128) void precomp_kernel(
    const float* __restrict__ W2a, const float* __restrict__ W1b,
    const float* __restrict__ b1b, const float* __restrict__ b2a,
    const float* __restrict__ u)
{
    int b = blockIdx.x, tid = threadIdx.x;
    if (b < 128) {
        int c = b;
        __shared__ float wa[128];
        wa[tid] = W2a[c * 320 + 128 + tid];
        __syncthreads();
        float acc = 0.f;
#pragma unroll 8
        for (int j = 0; j < 128; j++) acc += wa[j] * W1b[j * 128 + tid];
        g_Wcomb[c * 128 + tid] = acc;
        if (tid == 0) {
            float s = 0.f;
            for (int j = 0; j < 128; j++) s += wa[j] * b1b[j];
            g_v[c] = s;
        }
    } else {
        int g = b - 128, c = tid;
        float acc = b2a[c];
#pragma unroll 8
        for (int q = 0; q < 64; q++)
            acc += W2a[c * 320 + 256 + q] * u[g * 64 + q];
        g_U16[g * 128 + c] = acc;
    }
}

// ---------------- mma / ldmatrix helpers ----------------
__device__ __forceinline__ void ldmx4(unsigned& r0, unsigned& r1, unsigned& r2,
                                      unsigned& r3, const void* p) {
    unsigned a = (unsigned)__cvta_generic_to_shared(p);
    asm volatile("ldmatrix.sync.aligned.m8n8.x4.shared.b16 {%0,%1,%2,%3}, [%4];"
                 : "=r"(r0), "=r"(r1), "=r"(r2), "=r"(r3) : "r"(a));
}
__device__ __forceinline__ void mma_bf16(float* d, unsigned a0, unsigned a1,
                                         unsigned a2, unsigned a3,
                                         unsigned b0, unsigned b1) {
    asm volatile(
        "mma.sync.aligned.m16n8k16.row.col.f32.bf16.bf16.f32 "
        "{%0,%1,%2,%3}, {%4,%5,%6,%7}, {%8,%9}, {%0,%1,%2,%3};"
        : "+f"(d[0]), "+f"(d[1]), "+f"(d[2]), "+f"(d[3])
        : "r"(a0), "r"(a1), "r"(a2), "r"(a3), "r"(b0), "r"(b1));
}
__device__ __forceinline__ void split2(float x, float y, unsigned& hi, unsigned& lo) {
    __nv_bfloat16 hx = __float2bfloat16_rn(x), hy = __float2bfloat16_rn(y);
    __nv_bfloat16 lx = __float2bfloat16_rn(x - __bfloat162float(hx));
    __nv_bfloat16 ly = __float2bfloat16_rn(y - __bfloat162float(hy));
    __nv_bfloat162 h2, l2;
    h2.x = hx; h2.y = hy; l2.x = lx; l2.y = ly;
    hi = *(unsigned*)&h2;
    lo = *(unsigned*)&l2;
}

// SMEM layout for agg (bytes from dynamic base)
#define SMA_WHI 0
#define SMA_WLO 18432
#define SMA_AHI 36864
#define SMA_ALO 55296
#define SMA_S   73728              // 8 warps x [16][68] f32 = 34816
#define SMA_IDX 108544             // 3 x 128 int = 1536
#define SMA_TOTAL 110080

// ---------------------------------------------------------------------------
// Tensor-core aggregation over flat tiles of 128 sorted edges (mma.sync —
// tcgen05 unavailable: harness PTX targets compute_103, no 'a' features).
// Z = attr_tile @ W1a_x^T via 3-pass split-bf16 mma, processed in two 64-col
// halves (acc[8][4] = 32 regs -> 2 CTAs/SM); B fragments loaded as ldmx4
// pairs. Epilogue per half: + P[src] fp32, leaky, per-warp segmented reduce
// over sorted targets, float4 atomics.
// ---------------------------------------------------------------------------
__global__ __launch_bounds__(256, 2) void agg_kernel(
    const float* __restrict__ attr, const float* __restrict__ W1a)
{
    extern __shared__ __align__(16) char smag[];
    __nv_bfloat16* Whi = (__nv_bfloat16*)(smag + SMA_WHI);
    __nv_bfloat16* Wlo = (__nv_bfloat16*)(smag + SMA_WLO);
    __nv_bfloat16* Ahi = (__nv_bfloat16*)(smag + SMA_AHI);
    __nv_bfloat16* Alo = (__nv_bfloat16*)(smag + SMA_ALO);
    int* es = (int*)(smag + SMA_IDX);
    int* ss = es + 128;
    int* ts = ss + 128;

    int tid = threadIdx.x;
    int lane = tid & 31, w = tid >> 5;

    // Stage W1a[:,64:] as split bf16, layout [n=128][k=64], row stride 72
    for (int idx = tid; idx < 128 * 64; idx += 256) {
        int c = idx >> 6, k = idx & 63;
        float x = W1a[c * 128 + 64 + k];
        __nv_bfloat16 h = __float2bfloat16_rn(x);
        Whi[c * 72 + k] = h;
        Wlo[c * 72 + k] = __float2bfloat16_rn(x - __bfloat162float(h));
    }

    int a_row = ((lane >> 3) & 1) * 8 + (lane & 7);
    int a_kof = ((lane >> 4) & 1) * 8;
    int b_pair_off = 8 * ((lane >> 4) & 1) + (lane & 7);
    int b_kof = ((lane >> 3) & 1) * 8;
    int rowb = w * 16;
    int r0 = lane >> 2, c2 = 2 * (lane & 3);
    const float4* attr4 = (const float4*)attr;
    float* S = (float*)(smag + SMA_S) + w * 1088;  // [16][68] per warp

    for (int t = blockIdx.x; t < NTILE; t += gridDim.x) {
        int base = t * 128;
        __syncthreads();  // previous tile fully consumed
        if (tid < 128) {
            es[tid] = g_seid[base + tid];
            ss[tid] = g_ssrc[base + tid];
            ts[tid] = g_stgt[base + tid];
        }
        __syncthreads();
        // Gather 128 attr rows, split to bf16 hi/lo
        for (int i = tid; i < 2048; i += 256) {
            int r = i >> 4, q = i & 15;
            float4 v = attr4[(long long)es[r] * 16 + q];
            unsigned h01, l01, h23, l23;
            split2(v.x, v.y, h01, l01);
            split2(v.z, v.w, h23, l23);
            unsigned* dh = (unsigned*)(Ahi + r * 72 + 4 * q);
            unsigned* dl = (unsigned*)(Alo + r * 72 + 4 * q);
            dh[0] = h01; dh[1] = h23;
            dl[0] = l01; dl[1] = l23;
        }
        __syncthreads();

        int s0 = ss[rowb + r0], s1 = ss[rowb + r0 + 8];

#pragma unroll
        for (int half = 0; half < 2; half++) {
            float acc[8][4];
#pragma unroll
            for (int n = 0; n < 8; n++) {
                acc[n][0] = 0.f; acc[n][1] = 0.f;
                acc[n][2] = 0.f; acc[n][3] = 0.f;
            }

#pragma unroll
            for (int ks = 0; ks < 4; ks++) {
                unsigned ah0, ah1, ah2, ah3, al0, al1, al2, al3;
                const __nv_bfloat16* pa = Ahi + (rowb + a_row) * 72 + ks * 16 + a_kof;
                ldmx4(ah0, ah1, ah2, ah3, pa);
                const __nv_bfloat16* pl = Alo + (rowb + a_row) * 72 + ks * 16 + a_kof;
                ldmx4(al0, al1, al2, al3, pl);
#pragma unroll
                for (int np = 0; np < 8; np += 2) {
                    int nf = half * 8 + np;
                    unsigned bh0, bh1, bh2, bh3, bl0, bl1, bl2, bl3;
                    const __nv_bfloat16* pbh =
                        Whi + (8 * nf + b_pair_off) * 72 + ks * 16 + b_kof;
                    ldmx4(bh0, bh1, bh2, bh3, pbh);
                    const __nv_bfloat16* pbl =
                        Wlo + (8 * nf + b_pair_off) * 72 + ks * 16 + b_kof;
                    ldmx4(bl0, bl1, bl2, bl3, pbl);
                    mma_bf16(acc[np], ah0, ah1, ah2, ah3, bh0, bh1);
                    mma_bf16(acc[np], ah0, ah1, ah2, ah3, bl0, bl1);
                    mma_bf16(acc[np], al0, al1, al2, al3, bh0, bh1);
                    mma_bf16(acc[np + 1], ah0, ah1, ah2, ah3, bh2, bh3);
                    mma_bf16(acc[np + 1], ah0, ah1, ah2, ah3, bl2, bl3);
                    mma_bf16(acc[np + 1], al0, al1, al2, al3, bh2, bh3);
                }
            }

            // Epilogue for this 64-col half
#pragma unroll
            for (int nq = 0; nq < 8; nq++) {
                int gc = 64 * half + 8 * nq + c2;
                int lc = 8 * nq + c2;
                float2 p0 = *(const float2*)&g_P[(long long)s0 * 128 + gc];
                float2 p1 = *(const float2*)&g_P[(long long)s1 * 128 + gc];
                float z0 = acc[nq][0] + p0.x; z0 = z0 >= 0.f ? z0 : 0.1f * z0;
                float z1 = acc[nq][1] + p0.y; z1 = z1 >= 0.f ? z1 : 0.1f * z1;
                float z2 = acc[nq][2] + p1.x; z2 = z2 >= 0.f ? z2 : 0.1f * z2;
                float z3 = acc[nq][3] + p1.y; z3 = z3 >= 0.f ? z3 : 0.1f * z3;
                *(float2*)&S[r0 * 68 + lc] = make_float2(z0, z1);
                *(float2*)&S[(r0 + 8) * 68 + lc] = make_float2(z2, z3);
            }
            __syncwarp();
            if (lane < 16) {
                int i = 0;
                while (i < 16) {
                    int tg = ts[rowb + i];
                    float4 s4 = make_float4(0.f, 0.f, 0.f, 0.f);
                    int jr = i;
                    do {
                        float4 v = *(const float4*)&S[jr * 68 + 4 * lane];
                        s4.x += v.x; s4.y += v.y; s4.z += v.z; s4.w += v.w;
                        jr++;
                    } while (jr < 16 && ts[rowb + jr] == tg);
                    atomicAdd((float4*)&g_AGG[(long long)tg * 128 + 64 * half + 4 * lane], s4);
                    i = jr;
                }
            }
            __syncwarp();
        }
    }
}

// FMA micro-tile: acc[4][4] += a[e].{x,y,z,w} * w{0..3}.{col}
#define FMA_TILE(acc, a0, a1, a2, a3, w0, w1, w2, w3)                          \
    {                                                                          \
        float4 _a[4] = {a0, a1, a2, a3};                                       \
        _Pragma("unroll") for (int _e = 0; _e < 4; _e++) {                     \
            acc[_e][0] += _a[_e].x * w0.x + _a[_e].y * w1.x +                  \
                          _a[_e].z * w2.x + _a[_e].w * w3.x;                   \
            acc[_e][1] += _a[_e].x * w0.y + _a[_e].y * w1.y +                  \
                          _a[_e].z * w2.y + _a[_e].w * w3.y;                   \
            acc[_e][2] += _a[_e].x * w0.z + _a[_e].y * w1.z +                  \
                          _a[_e].z * w2.z + _a[_e].w * w3.z;                   \
            acc[_e][3] += _a[_e].x * w0.w + _a[_e].y * w1.w +                  \
                          _a[_e].z * w2.w + _a[_e].w * w3.w;                   \
        }                                                                      \
    }

// ---------------------------------------------------------------------------
// Row GEMM: out[n][c] = in[n,:K] . W[c,:K] + bias.
// MODE 0: plain.  MODE 2: plain + edge-histogram prologue (fused hist).
// ---------------------------------------------------------------------------
template <int K, int MODE>
__global__ __launch_bounds__(256) void row_kernel(
    const float* __restrict__ in, const float* __restrict__ W,
    const float* __restrict__ bvec, float* __restrict__ out, int N,
    const int* __restrict__ eidx)
{
    if (MODE == 2) {
        int gidx = blockIdx.x * blockDim.x + threadIdx.x;
        for (int e = gidx; e < NEDGE; e += gridDim.x * blockDim.x)
            atomicAdd(&g_hist[eidx[NEDGE + e]], 1);
    }
    extern __shared__ __align__(16) float smrow[];
    constexpr int K4 = K / 4;
    float* Wt = smrow;               // [K][128]
    float* in_s = smrow + K * 128;   // [32][K]
    int tid = threadIdx.x;
    int j = tid & 31, m = tid >> 5;

    for (int idx = tid; idx < K * 128; idx += 256) {
        int k = idx % K, c = idx / K;
        Wt[k * 128 + c] = W[c * 128 + k];
    }
    __syncthreads();

    float4 b4 = *(const float4*)&bvec[4 * j];
    const float4* Wt4 = (const float4*)Wt;
    const float4* is4 = (const float4*)in_s;
    int nt = (N + 31) >> 5;

    for (int t = blockIdx.x; t < nt; t += gridDim.x) {
        int base = t * 32;
        for (int idx = tid; idx < 32 * K4; idx += 256) {
            int r = idx / K4, kq = idx % K4;
            int rg = base + r; if (rg > N - 1) rg = N - 1;
            ((float4*)in_s)[idx] = ((const float4*)in)[(long long)rg * K4 + kq];
        }
        __syncthreads();

        float acc[4][4] = {};
#pragma unroll 8
        for (int k4 = 0; k4 < K4; k4++) {
            float4 a0 = is4[(4 * m + 0) * K4 + k4];
            float4 a1 = is4[(4 * m + 1) * K4 + k4];
            float4 a2 = is4[(4 * m + 2) * K4 + k4];
            float4 a3 = is4[(4 * m + 3) * K4 + k4];
            float4 w0 = Wt4[(4 * k4 + 0) * 32 + j];
            float4 w1 = Wt4[(4 * k4 + 1) * 32 + j];
            float4 w2 = Wt4[(4 * k4 + 2) * 32 + j];
            float4 w3 = Wt4[(4 * k4 + 3) * 32 + j];
            FMA_TILE(acc, a0, a1, a2, a3, w0, w1, w2, w3)
        }
#pragma unroll
        for (int e = 0; e < 4; e++) {
            int r = base + 4 * m + e;
            if (r < N) {
                float4 v;
                v.x = acc[e][0] + b4.x;
                v.y = acc[e][1] + b4.y;
                v.z = acc[e][2] + b4.z;
                v.w = acc[e][3] + b4.w;
                *(float4*)&out[(long long)r * 128 + 4 * j] = v;
            }
        }
        __syncthreads();
    }
}

// ---------------------------------------------------------------------------
// Fused node MLP hidden: H = leaky([x_g | AGG] @ [Wg | Wcomb]^T
//                                  + cnt*v + U16[batch]), K = 256.
// Reads g_AGG and restores it to zero (replay protocol).
// ---------------------------------------------------------------------------
__global__ __launch_bounds__(256) void nodeH2_kernel(
    const float* __restrict__ xg, const int* __restrict__ batch,
    const float* __restrict__ W2a, int N)
{
    extern __shared__ __align__(16) float smnh[];
    float* Wt = smnh;                 // [256][128]
    float* in_s = smnh + 256 * 128;   // [32][256]
    int tid = threadIdx.x;
    int j = tid & 31, m = tid >> 5;

    for (int idx = tid; idx < 256 * 128; idx += 256) {
        int k = idx % 256, c = idx / 256;
        float val = (k < 128) ? W2a[c * 320 + k] : g_Wcomb[c * 128 + (k - 128)];
        Wt[k * 128 + c] = val;
    }
    __syncthreads();

    float4 v4 = *(const float4*)&g_v[4 * j];
    const float4* Wt4 = (const float4*)Wt;
    const float4* is4 = (const float4*)in_s;
    int nt = (N + 31) >> 5;

    for (int t = blockIdx.x; t < nt; t += gridDim.x) {
        int base = t * 32;
        for (int idx = tid; idx < 32 * 64; idx += 256) {
            int r = idx >> 6, q = idx & 63;
            int rg = base + r; if (rg > N - 1) rg = N - 1;
            float4 v;
            if (q < 32) v = ((const float4*)xg)[(long long)rg * 32 + q];
            else {
                v = ((const float4*)g_AGG)[(long long)rg * 32 + (q - 32)];
                ((float4*)g_AGG)[(long long)rg * 32 + (q - 32)] =
                    make_float4(0.f, 0.f, 0.f, 0.f);  // replay restore
            }
            ((float4*)in_s)[idx] = v;
        }
        __syncthreads();

        float acc[4][4] = {};
#pragma unroll 8
        for (int k4 = 0; k4 < 64; k4++) {
            float4 a0 = is4[(4 * m + 0) * 64 + k4];
            float4 a1 = is4[(4 * m + 1) * 64 + k4];
            float4 a2 = is4[(4 * m + 2) * 64 + k4];
            float4 a3 = is4[(4 * m + 3) * 64 + k4];
            float4 w0 = Wt4[(4 * k4 + 0) * 32 + j];
            float4 w1 = Wt4[(4 * k4 + 1) * 32 + j];
            float4 w2 = Wt4[(4 * k4 + 2) * 32 + j];
            float4 w3 = Wt4[(4 * k4 + 3) * 32 + j];
            FMA_TILE(acc, a0, a1, a2, a3, w0, w1, w2, w3)
        }
#pragma unroll
        for (int e = 0; e < 4; e++) {
            int r = base + 4 * m + e;
            if (r < N) {
                float cnt = g_CNT[r];
                float4 uu = *(const float4*)&g_U16[batch[r] * 128 + 4 * j];
                float4 v;
                v.x = acc[e][0] + cnt * v4.x + uu.x; v.x = v.x >= 0.f ? v.x : 0.1f * v.x;
                v.y = acc[e][1] + cnt * v4.y + uu.y; v.y = v.y >= 0.f ? v.y : 0.1f * v.y;
                v.z = acc[e][2] + cnt * v4.z + uu.z; v.z = v.z >= 0.f ? v.z : 0.1f * v.z;
                v.w = acc[e][3] + cnt * v4.w + uu.w; v.w = v.w >= 0.f ? v.w : 0.1f * v.w;
                *(float4*)&g_H[(long long)r * 128 + 4 * j] = v;
            }
        }
        __syncthreads();
    }
}

extern "C" void kernel_launch(void* const* d_in, const int* in_sizes, int n_in,
                              void* d_out, int out_size)
{
    const float* x_h = (const float*)d_in[0];
    const float* x_g = (const float*)d_in[1];
    const float* eattr = (const float*)d_in[2];
    const float* u = (const float*)d_in[3];
    const float* W1a = (const float*)d_in[4];
    const float* b1a = (const float*)d_in[5];
    const float* W1b = (const float*)d_in[6];
    const float* b1b = (const float*)d_in[7];
    const float* W2a = (const float*)d_in[8];
    const float* b2a = (const float*)d_in[9];
    const float* W2b = (const float*)d_in[10];
    const float* b2b = (const float*)d_in[11];
    const int* eidx = (const int*)d_in[12];   // int32
    const int* batch = (const int*)d_in[13];  // int32
    float* out = (float*)d_out;

    float *pP, *pH;
    cudaGetSymbolAddress((void**)&pP, g_P);
    cudaGetSymbolAddress((void**)&pH, g_H);

    size_t smem64 = (size_t)(64 * 128 + 32 * 64) * 4;
    size_t smem128 = (size_t)(128 * 128 + 32 * 128) * 4;
    size_t smem256 = (size_t)(256 * 128 + 32 * 256) * 4;
    cudaFuncSetAttribute(row_kernel<64, 2>,
                         cudaFuncAttributeMaxDynamicSharedMemorySize, (int)smem64);
    cudaFuncSetAttribute(row_kernel<128, 0>,
                         cudaFuncAttributeMaxDynamicSharedMemorySize, (int)smem128);
    cudaFuncSetAttribute(nodeH2_kernel,
                         cudaFuncAttributeMaxDynamicSharedMemorySize, (int)smem256);
    cudaFuncSetAttribute(agg_kernel,
                         cudaFuncAttributeMaxDynamicSharedMemorySize, SMA_TOTAL);

    // 1: P = x_h @ W1a[:, :64]^T + b1a  (+ fused edge histogram)
    row_kernel<64, 2><<<1563, 256, smem64>>>(x_h, W1a, b1a, pP, NHN, eidx);
    // 2: scan (reads + re-zeroes hist; emits off/cursor/CNT)
    scan_kernel<<<1, 1024>>>();
    // 3: counting-sort permute
    permute_kernel<<<1184, 256>>>(eidx);
    // 4: aggregation (PROFILED LAUNCH)
    agg_kernel<<<296, 256, SMA_TOTAL>>>(eattr, W1a);
    // 5: fold A-step: Wcomb = Wa@W1b, v = Wa@b1b, U16 = u@W2a_u^T + b2a
    precomp_kernel<<<144, 128>>>(W2a, W1b, b1b, b2a, u);
    // 6: H = leaky([x_g | AGG] @ [Wg|Wcomb]^T + cnt*v + U16[batch])
    nodeH2_kernel<<<1563, 256, smem256>>>(x_g, batch, W2a, NGN);
    // 7: out = H @ W2b^T + b2b
    row_kernel<128, 0><<<1563, 256, smem128>>>(pH, W2b, b2b, out, NGN, nullptr);
}